// round 7
// baseline (speedup 1.0000x reference)
#include <cuda_runtime.h>
#include <math.h>

#define B_  2
#define T_  2048
#define DM  1024
#define H_  16
#define DH  64
#define BT  (B_ * T_)   // 4096

// ---------------- scratch (static device globals; no runtime alloc) ----------
__device__ float g_Q[(long long)BT * DM];     // 16.8 MB
__device__ float g_K[(long long)BT * DM];     // 16.8 MB
__device__ float g_Vs[(long long)BT * DH];    // 1 MB
__device__ float g_m[B_ * H_ * T_];
__device__ float g_l[B_ * H_ * T_];
__device__ float g_o1[(long long)BT * DH];    // 1 MB

// ---------------- zero helper -----------------------------------------------
__global__ void zero_kernel(float* p, long long n4)   // n4 = count of float4
{
    long long i = blockIdx.x * (long long)blockDim.x + threadIdx.x;
    long long stride = (long long)gridDim.x * blockDim.x;
    float4 z = make_float4(0.f, 0.f, 0.f, 0.f);
    for (; i < n4; i += stride)
        ((float4*)p)[i] = z;
}

// ---------------- double-buffered SGEMM: C = A[MxK] * B[KxN] ----------------
// 128x128 tile, BK=8, 256 threads, 8x8/thread. Optional dual-pointer mode
// (blockIdx.z==1 selects the second set) for fusing the Q and K projections.
__global__ __launch_bounds__(256) void sgemm_db(
    const float* __restrict__ A,  const float* __restrict__ Bm,  float* __restrict__ C,
    const float* __restrict__ A2, const float* __restrict__ B2,  float* __restrict__ C2,
    int M, int N, int K)
{
    const float* Ap = A;
    const float* Bp = Bm;
    float*       Cp = C;
    if (A2 != nullptr && blockIdx.z == 1) { Ap = A2; Bp = B2; Cp = C2; }

    __shared__ float As[2][8][132];
    __shared__ float Bs[2][8][132];

    const int t  = threadIdx.x;
    const int tx = t % 16;
    const int ty = t / 16;
    const int m0 = blockIdx.y * 128;
    const int n0 = blockIdx.x * 128;

    float acc[8][8];
#pragma unroll
    for (int i = 0; i < 8; i++)
#pragma unroll
        for (int j = 0; j < 8; j++) acc[i][j] = 0.f;

    float ra[4], rb[4];
    const int nk = K / 8;

    // prologue: load tile 0
#pragma unroll
    for (int p = 0; p < 4; p++) {
        int idx = t + 256 * p;
        int m = idx >> 3, kk = idx & 7;
        int gm = m0 + m;
        ra[p] = (gm < M) ? Ap[(long long)gm * K + kk] : 0.f;
    }
#pragma unroll
    for (int p = 0; p < 4; p++) {
        int idx = t + 256 * p;
        int kk = idx >> 7, n = idx & 127;
        int gn = n0 + n;
        rb[p] = (gn < N) ? Bp[(long long)kk * N + gn] : 0.f;
    }
#pragma unroll
    for (int p = 0; p < 4; p++) {
        int idx = t + 256 * p;
        As[0][idx & 7][idx >> 3] = ra[p];
        Bs[0][idx >> 7][idx & 127] = rb[p];
    }
    __syncthreads();

    for (int kt = 0; kt < nk; kt++) {
        const int cur = kt & 1;
        const int k0n = (kt + 1) * 8;
        if (kt + 1 < nk) {
#pragma unroll
            for (int p = 0; p < 4; p++) {
                int idx = t + 256 * p;
                int m = idx >> 3, kk = idx & 7;
                int gm = m0 + m;
                ra[p] = (gm < M) ? Ap[(long long)gm * K + (k0n + kk)] : 0.f;
            }
#pragma unroll
            for (int p = 0; p < 4; p++) {
                int idx = t + 256 * p;
                int kk = idx >> 7, n = idx & 127;
                int gn = n0 + n;
                rb[p] = (gn < N) ? Bp[(long long)(k0n + kk) * N + gn] : 0.f;
            }
        }

#pragma unroll
        for (int kk = 0; kk < 8; kk++) {
            float a[8], b[8];
#pragma unroll
            for (int i = 0; i < 4; i++) {
                a[i]     = As[cur][kk][ty * 4 + i];
                a[4 + i] = As[cur][kk][64 + ty * 4 + i];
            }
#pragma unroll
            for (int j = 0; j < 4; j++) {
                b[j]     = Bs[cur][kk][tx * 4 + j];
                b[4 + j] = Bs[cur][kk][64 + tx * 4 + j];
            }
#pragma unroll
            for (int i = 0; i < 8; i++)
#pragma unroll
                for (int j = 0; j < 8; j++)
                    acc[i][j] += a[i] * b[j];
        }

        if (kt + 1 < nk) {
#pragma unroll
            for (int p = 0; p < 4; p++) {
                int idx = t + 256 * p;
                As[cur ^ 1][idx & 7][idx >> 3] = ra[p];
                Bs[cur ^ 1][idx >> 7][idx & 127] = rb[p];
            }
            __syncthreads();
        }
    }

#pragma unroll
    for (int i = 0; i < 8; i++) {
        int gm = m0 + ((i < 4) ? (ty * 4 + i) : (64 + ty * 4 + (i - 4)));
        if (gm >= M) continue;
#pragma unroll
        for (int j = 0; j < 8; j++) {
            int gn = n0 + ((j < 4) ? (tx * 4 + j) : (64 + tx * 4 + (j - 4)));
            if (gn < N) Cp[(long long)gm * N + gn] = acc[i][j];
        }
    }
}

// ---------------- V projection: [4096x1024]@[1024x64], split-K=4, atomic ----
__global__ __launch_bounds__(256) void vproj_n64(
    const float* __restrict__ A, const float* __restrict__ Bm)
{
    const int m0   = blockIdx.x * 128;
    const int kBeg = blockIdx.y * (DM / 4);
    const int kEnd = kBeg + DM / 4;

    __shared__ float As[8][132];
    __shared__ float Bs[8][68];

    const int t  = threadIdx.x;
    const int tx = t & 15;
    const int ty = t >> 4;

    float acc[8][4];
#pragma unroll
    for (int v = 0; v < 8; v++)
#pragma unroll
        for (int u = 0; u < 4; u++) acc[v][u] = 0.f;

    for (int k0 = kBeg; k0 < kEnd; k0 += 8) {
#pragma unroll
        for (int p = 0; p < 4; p++) {
            int idx = t + 256 * p;
            int m = idx >> 3, kk = idx & 7;
            As[kk][m] = A[(long long)(m0 + m) * DM + k0 + kk];
        }
#pragma unroll
        for (int p = 0; p < 2; p++) {
            int idx = t + 256 * p;
            int kk = idx >> 6, n = idx & 63;
            Bs[kk][n] = Bm[(long long)(k0 + kk) * DH + n];
        }
        __syncthreads();
#pragma unroll
        for (int kk = 0; kk < 8; kk++) {
            float bv[4];
#pragma unroll
            for (int u = 0; u < 4; u++) bv[u] = Bs[kk][tx + 16 * u];
#pragma unroll
            for (int v = 0; v < 8; v++) {
                float av = As[kk][ty + 16 * v];
#pragma unroll
                for (int u = 0; u < 4; u++) acc[v][u] += av * bv[u];
            }
        }
        __syncthreads();
    }

#pragma unroll
    for (int v = 0; v < 8; v++)
#pragma unroll
        for (int u = 0; u < 4; u++)
            atomicAdd(&g_Vs[(long long)(m0 + ty + 16 * v) * DH + tx + 16 * u],
                      acc[v][u]);
}

// ---------------- triangular attn@V: split-K with diagonal skip ------------
// grid (jc=16, ib=16, b=2); block active iff jc <= ib. 128-row x 64-col tile,
// K-chunk of 128 attn columns. Accumulate into zeroed g_o1 via atomicAdd.
__global__ __launch_bounds__(256) void tri_av(const float* __restrict__ attn)
{
    const int jc = blockIdx.x;
    const int ib = blockIdx.y;
    if (jc > ib) return;
    const int b  = blockIdx.z;

    const float* A  = attn + (long long)b * T_ * T_;
    const float* Bv = g_Vs + (long long)b * T_ * DH;
    float*       C  = g_o1 + (long long)b * T_ * DH;

    const int i0   = ib * 128;
    const int kBeg = jc * 128;

    __shared__ float As[8][132];
    __shared__ float Bs[8][68];

    const int t  = threadIdx.x;
    const int tx = t & 15;
    const int ty = t >> 4;

    float acc[8][4];
#pragma unroll
    for (int v = 0; v < 8; v++)
#pragma unroll
        for (int u = 0; u < 4; u++) acc[v][u] = 0.f;

    for (int k0 = kBeg; k0 < kBeg + 128; k0 += 8) {
#pragma unroll
        for (int p = 0; p < 4; p++) {
            int idx = t + 256 * p;
            int m = idx >> 3, kk = idx & 7;
            As[kk][m] = A[(long long)(i0 + m) * T_ + k0 + kk];
        }
#pragma unroll
        for (int p = 0; p < 2; p++) {
            int idx = t + 256 * p;
            int kk = idx >> 6, n = idx & 63;
            Bs[kk][n] = Bv[(long long)(k0 + kk) * DH + n];
        }
        __syncthreads();
#pragma unroll
        for (int kk = 0; kk < 8; kk++) {
            float bv[4];
#pragma unroll
            for (int u = 0; u < 4; u++) bv[u] = Bs[kk][tx + 16 * u];
#pragma unroll
            for (int v = 0; v < 8; v++) {
                float av = As[kk][ty + 16 * v];
#pragma unroll
                for (int u = 0; u < 4; u++) acc[v][u] += av * bv[u];
            }
        }
        __syncthreads();
    }

#pragma unroll
    for (int v = 0; v < 8; v++)
#pragma unroll
        for (int u = 0; u < 4; u++)
            atomicAdd(&C[(long long)(i0 + ty + 16 * v) * DH + tx + 16 * u],
                      acc[v][u]);
}

// ---------------- pass A: per-(b,h,row) online softmax stats ----------------
// 128q x 128k tiles, 8q x 8k per thread (strided). LPT remap: longest first.
#define PA_LD 68
__global__ __launch_bounds__(256) void pass_a()
{
    extern __shared__ float sm[];
    float* Qs = sm;                    // [128][68]
    float* Ks = sm + 128 * PA_LD;      // [128][68]

    const int i0 = (15 - blockIdx.x) * 128;   // descending work size
    const int h  = blockIdx.y;
    const int b  = blockIdx.z;
    const int t  = threadIdx.x;
    const int tx = t & 15;             // k group
    const int ty = t >> 4;             // q group

    const float* Qbase = g_Q + ((long long)(b * T_ + i0)) * DM + h * DH;
    const float* Kbase = g_K + ((long long)(b * T_)) * DM + h * DH;

#pragma unroll
    for (int p = 0; p < 8; p++) {
        int idx = t + 256 * p;
        int rr = idx >> 4, dq = (idx & 15) * 4;
        *(float4*)&Qs[rr * PA_LD + dq] =
            *(const float4*)&Qbase[(long long)rr * DM + dq];
    }

    float m_run[8], l_run[8];
#pragma unroll
    for (int v = 0; v < 8; v++) { m_run[v] = -INFINITY; l_run[v] = 0.f; }

    for (int jt = 0; jt <= i0; jt += 128) {
        __syncthreads();
#pragma unroll
        for (int p = 0; p < 8; p++) {
            int idx = t + 256 * p;
            int rr = idx >> 4, dq = (idx & 15) * 4;
            *(float4*)&Ks[rr * PA_LD + dq] =
                *(const float4*)&Kbase[(long long)(jt + rr) * DM + dq];
        }
        __syncthreads();

        float s[8][8];
#pragma unroll
        for (int v = 0; v < 8; v++)
#pragma unroll
            for (int u = 0; u < 8; u++) s[v][u] = 0.f;

        const float* kp = &Ks[tx * PA_LD];
        const float* qp = &Qs[ty * PA_LD];
#pragma unroll 2
        for (int d = 0; d < 64; d += 4) {
            float4 kv[8];
#pragma unroll
            for (int u = 0; u < 8; u++)
                kv[u] = *(const float4*)&kp[u * 16 * PA_LD + d];
#pragma unroll
            for (int v = 0; v < 8; v++) {
                float4 qv = *(const float4*)&qp[v * 16 * PA_LD + d];
#pragma unroll
                for (int u = 0; u < 8; u++) {
                    s[v][u] += qv.x * kv[u].x;
                    s[v][u] += qv.y * kv[u].y;
                    s[v][u] += qv.z * kv[u].z;
                    s[v][u] += qv.w * kv[u].w;
                }
            }
        }

        const bool diag = (jt == i0);
#pragma unroll
        for (int v = 0; v < 8; v++) {
            const int i = i0 + ty + 16 * v;
            float tmax = -INFINITY;
#pragma unroll
            for (int u = 0; u < 8; u++) {
                float sv = s[v][u] * 0.125f;
                if (diag && (jt + tx + 16 * u) > i) sv = -INFINITY;
                s[v][u] = sv;
                tmax = fmaxf(tmax, sv);
            }
#pragma unroll
            for (int o = 1; o < 16; o <<= 1)
                tmax = fmaxf(tmax, __shfl_xor_sync(0xffffffffu, tmax, o));

            float nm = fmaxf(m_run[v], tmax);
            float ps = 0.f;
#pragma unroll
            for (int u = 0; u < 8; u++) ps += __expf(s[v][u] - nm);
#pragma unroll
            for (int o = 1; o < 16; o <<= 1)
                ps += __shfl_xor_sync(0xffffffffu, ps, o);
            l_run[v] = l_run[v] * __expf(m_run[v] - nm) + ps;
            m_run[v] = nm;
        }
    }

    if (tx == 0) {
#pragma unroll
        for (int v = 0; v < 8; v++) {
            int i = i0 + ty + 16 * v;
            g_m[(b * H_ + h) * T_ + i] = m_run[v];
            g_l[(b * H_ + h) * T_ + i] = l_run[v];
        }
    }
}

// ---------------- pass B: head-averaged attention (lower-tri tiles only) ----
// grid (272, B). x enumerates lower-triangular (p=i-block, jb=j-tile) pairs.
__global__ __launch_bounds__(256) void pass_b(float* __restrict__ attn)
{
    extern __shared__ float sm[];
    float* Qs = sm;                          // [128][68]
    float* Ks = sm + 128 * PA_LD;            // [64][68]
    float* ms = sm + 192 * PA_LD;            // [16][128]
    float* cs = ms + 16 * 128;               // [16][128]

    // triangular index: tile (p, jb) with jb in [0, 2p+2), start(p)=p*p+p
    const int tIdx = blockIdx.x;
    int p = (int)((sqrtf(4.f * tIdx + 1.f) - 1.f) * 0.5f);
    while (p * p + p > tIdx) p--;
    while ((p + 1) * (p + 1) + (p + 1) <= tIdx) p++;
    const int jb = tIdx - (p * p + p);

    const int i0 = p * 128;
    const int j0 = jb * 64;
    const int b  = blockIdx.y;
    const int t  = threadIdx.x;
    const int tx = t & 15;                   // k group
    const int ty = t >> 4;                   // q group

    // preload softmax stats for this i-block, all heads
    for (int q = t; q < H_ * 128; q += 256) {
        int hh = q >> 7, rr = q & 127;
        ms[q] = g_m[(b * H_ + hh) * T_ + i0 + rr];
        cs[q] = 1.f / (16.f * g_l[(b * H_ + hh) * T_ + i0 + rr]);
    }

    const bool need_mask = (j0 + 63 > i0);

    float a[8][4];
#pragma unroll
    for (int v = 0; v < 8; v++)
#pragma unroll
        for (int u = 0; u < 4; u++) a[v][u] = 0.f;

    for (int h = 0; h < H_; h++) {
        __syncthreads();
        const float* Qbase = g_Q + ((long long)(b * T_ + i0)) * DM + h * DH;
        const float* Kbase = g_K + ((long long)(b * T_ + j0)) * DM + h * DH;
#pragma unroll
        for (int q = 0; q < 8; q++) {
            int idx = t + 256 * q;
            int rr = idx >> 4, dq = (idx & 15) * 4;
            *(float4*)&Qs[rr * PA_LD + dq] =
                *(const float4*)&Qbase[(long long)rr * DM + dq];
        }
#pragma unroll
        for (int q = 0; q < 4; q++) {
            int idx = t + 256 * q;
            int rr = idx >> 4, dq = (idx & 15) * 4;
            *(float4*)&Ks[rr * PA_LD + dq] =
                *(const float4*)&Kbase[(long long)rr * DM + dq];
        }
        __syncthreads();

        float s[8][4];
#pragma unroll
        for (int v = 0; v < 8; v++)
#pragma unroll
            for (int u = 0; u < 4; u++) s[v][u] = 0.f;

        const float* kp = &Ks[tx * PA_LD];
        const float* qp = &Qs[ty * PA_LD];
#pragma unroll 2
        for (int d = 0; d < 64; d += 4) {
            float4 kv[4];
#pragma unroll
            for (int u = 0; u < 4; u++)
                kv[u] = *(const float4*)&kp[u * 16 * PA_LD + d];
#pragma unroll
            for (int v = 0; v < 8; v++) {
                float4 qv = *(const float4*)&qp[v * 16 * PA_LD + d];
#pragma unroll
                for (int u = 0; u < 4; u++) {
                    s[v][u] += qv.x * kv[u].x;
                    s[v][u] += qv.y * kv[u].y;
                    s[v][u] += qv.z * kv[u].z;
                    s[v][u] += qv.w * kv[u].w;
                }
            }
        }

#pragma unroll
        for (int v = 0; v < 8; v++) {
            const int i  = i0 + ty + 16 * v;
            const float mh   = ms[h * 128 + ty + 16 * v];
            const float coef = cs[h * 128 + ty + 16 * v];
            if (need_mask) {
#pragma unroll
                for (int u = 0; u < 4; u++) {
                    int j = j0 + tx + 16 * u;
                    if (j <= i)
                        a[v][u] += __expf(s[v][u] * 0.125f - mh) * coef;
                }
            } else {
#pragma unroll
                for (int u = 0; u < 4; u++)
                    a[v][u] += __expf(s[v][u] * 0.125f - mh) * coef;
            }
        }
    }

#pragma unroll
    for (int v = 0; v < 8; v++) {
        const int i = i0 + ty + 16 * v;
        float* orow = attn + ((long long)(b * T_ + i)) * T_;
#pragma unroll
        for (int u = 0; u < 4; u++)
            orow[j0 + tx + 16 * u] = a[v][u];
    }
}

// ---------------- launch ----------------------------------------------------
extern "C" void kernel_launch(void* const* d_in, const int* in_sizes, int n_in,
                              void* d_out, int out_size)
{
    const float* q  = (const float*)d_in[0];
    const float* k  = (const float*)d_in[1];
    const float* v  = (const float*)d_in[2];
    // d_in[3] = mask (tril) — causality applied analytically
    const float* Wq = (const float*)d_in[4];
    const float* Wk = (const float*)d_in[5];
    const float* Wv = (const float*)d_in[6];
    const float* Wo = (const float*)d_in[7];

    float* out  = (float*)d_out;
    float* attn = out + (long long)BT * DM;

    float *Qp, *Kp, *Vp, *O1p;
    cudaGetSymbolAddress((void**)&Qp,  g_Q);
    cudaGetSymbolAddress((void**)&Kp,  g_K);
    cudaGetSymbolAddress((void**)&Vp,  g_Vs);
    cudaGetSymbolAddress((void**)&O1p, g_o1);

    const int smem_a = 2 * 128 * PA_LD * 4;                       // 69632
    const int smem_b = (192 * PA_LD + 2 * 16 * 128) * 4;          // 68608
    static bool attr_set = false;
    if (!attr_set) {
        cudaFuncSetAttribute(pass_a, cudaFuncAttributeMaxDynamicSharedMemorySize, smem_a);
        cudaFuncSetAttribute(pass_b, cudaFuncAttributeMaxDynamicSharedMemorySize, smem_b);
        attr_set = true;
    }

    // 0: zero accumulation buffers + attn upper triangle (full memset of attn)
    zero_kernel<<<4096, 256>>>(attn, (long long)BT * T_ / 4);
    zero_kernel<<<256, 256>>>(Vp,  (long long)BT * DH / 4);
    zero_kernel<<<256, 256>>>(O1p, (long long)BT * DH / 4);

    // 1: fused Q and K projections (z=0 -> Q set, z=1 -> K set)
    sgemm_db<<<dim3(DM / 128, BT / 128, 2), 256>>>(q, Wq, Qp, k, Wk, Kp,
                                                   BT, DM, DM);

    // 2: V projection, split-K=4, atomic accumulate
    vproj_n64<<<dim3(BT / 128, 4), 256>>>(v, Wv);

    // 3: softmax stats (LPT-ordered)
    pass_a<<<dim3(T_ / 128, H_, B_), 256, smem_a>>>();

    // 4: head-averaged attention matrix, lower-tri tiles only
    pass_b<<<dim3(272, B_), 256, smem_b>>>(attn);

    // 5: out1 = attn_avg @ V_shared (triangular split-K, atomic)
    tri_av<<<dim3(16, 16, B_), 256>>>(attn);

    // 6: out = out1 @ Wo
    sgemm_db<<<dim3(DM / 128, BT / 128, 1), 256>>>(O1p, Wo, out,
                                                   nullptr, nullptr, nullptr,
                                                   BT, DM, DH);
}

// round 10
// speedup vs baseline: 1.2781x; 1.2781x over previous
#include <cuda_runtime.h>
#include <cstdint>
#include <stdint.h>
#include <math.h>

#define B_  2
#define T_  2048
#define DM  1024
#define H_  16
#define DH  64
#define BT  (B_ * T_)   // 4096

// ---------------- scratch (static device globals; no runtime alloc) ----------
__device__ float g_Q[(long long)BT * DM];     // 16.8 MB
__device__ float g_K[(long long)BT * DM];     // 16.8 MB
__device__ float g_Vs[(long long)BT * DH];    // 1 MB
__device__ float g_m[B_ * H_ * T_];
__device__ float g_l[B_ * H_ * T_];
__device__ float g_o1[(long long)BT * DH];    // 1 MB

// ---------------- tf32 helpers ----------------------------------------------
__device__ __forceinline__ void split_tf32(float x, unsigned int& hi, unsigned int& lo) {
    unsigned int h;
    asm("cvt.rna.tf32.f32 %0, %1;" : "=r"(h) : "f"(x));
    float l = x - __uint_as_float(h);
    unsigned int lr;
    asm("cvt.rna.tf32.f32 %0, %1;" : "=r"(lr) : "f"(l));
    hi = h; lo = lr;
}

__device__ __forceinline__ void mma_tf32(float* c, const unsigned int* a, const unsigned int* b) {
    asm volatile(
        "mma.sync.aligned.m16n8k8.row.col.f32.tf32.tf32.f32 "
        "{%0,%1,%2,%3}, {%4,%5,%6,%7}, {%8,%9}, {%0,%1,%2,%3};"
        : "+f"(c[0]), "+f"(c[1]), "+f"(c[2]), "+f"(c[3])
        : "r"(a[0]), "r"(a[1]), "r"(a[2]), "r"(a[3]),
          "r"(b[0]), "r"(b[1]));
}

// ---------------- split-tf32 projection GEMM --------------------------------
// C[4096x1024] = A[4096x1024] @ B[1024x1024].  blockIdx.z selects (A,B,C) set.
// 128x128 block tile, BK=16, 256 threads (8 warps, 2m x 4n), 64x32 warp tile.
// 3-term split-tf32: AhBh + AhBl + AlBh (error ~2^-22).
#define MM_LDS 136
__global__ __launch_bounds__(256, 2) void mmproj(
    const float* __restrict__ A,  const float* __restrict__ Bm,  float* __restrict__ C,
    const float* __restrict__ A2, const float* __restrict__ B2,  float* __restrict__ C2)
{
    if (blockIdx.z == 1) { A = A2; Bm = B2; C = C2; }
    const int K = DM, N = DM;

    __shared__ float Ah[16][MM_LDS], Al[16][MM_LDS];
    __shared__ float Bh[16][MM_LDS], Bl[16][MM_LDS];

    const int t    = threadIdx.x;
    const int wid  = t >> 5;
    const int lane = t & 31;
    const int g    = lane >> 2;       // group id (0..7)
    const int tg   = lane & 3;        // thread-in-group
    const int wm   = (wid >> 2) * 64; // warp m offset
    const int wn   = (wid & 3) * 32;  // warp n offset
    const int m0   = blockIdx.y * 128;
    const int n0   = blockIdx.x * 128;

    float acc[4][4][4];
#pragma unroll
    for (int mi = 0; mi < 4; mi++)
#pragma unroll
        for (int ni = 0; ni < 4; ni++)
#pragma unroll
            for (int e = 0; e < 4; e++) acc[mi][ni][e] = 0.f;

    // per-thread load coords
    const int am = t & 127;            // A row within tile
    const int ak = (t >> 7) * 8;       // A k offset (0 or 8)
    const int bk = t >> 4;             // B k row (0..15)
    const int bn = (t & 15) * 4;       // B n offset (float4)

    for (int k0 = 0; k0 < K; k0 += 16) {
        // global loads first (latency overlap)
        float4 av0 = *(const float4*)&A [(long long)(m0 + am) * K + k0 + ak];
        float4 av1 = *(const float4*)&A [(long long)(m0 + am) * K + k0 + ak + 4];
        float4 bv0 = *(const float4*)&Bm[(long long)(k0 + bk) * N + n0 + bn];
        float4 bv1 = *(const float4*)&Bm[(long long)(k0 + bk) * N + n0 + 64 + bn];

        __syncthreads();   // previous tile fully consumed

        // A: transpose-store with split
        {
            float va[8] = {av0.x, av0.y, av0.z, av0.w, av1.x, av1.y, av1.z, av1.w};
#pragma unroll
            for (int i = 0; i < 8; i++) {
                unsigned int h, l;
                split_tf32(va[i], h, l);
                Ah[ak + i][am] = __uint_as_float(h);
                Al[ak + i][am] = __uint_as_float(l);
            }
        }
        // B: row-store with split (float4)
        {
            float vb0[4] = {bv0.x, bv0.y, bv0.z, bv0.w};
            float vb1[4] = {bv1.x, bv1.y, bv1.z, bv1.w};
            float h0[4], l0[4], h1[4], l1[4];
#pragma unroll
            for (int i = 0; i < 4; i++) {
                unsigned int h, l;
                split_tf32(vb0[i], h, l); h0[i] = __uint_as_float(h); l0[i] = __uint_as_float(l);
                split_tf32(vb1[i], h, l); h1[i] = __uint_as_float(h); l1[i] = __uint_as_float(l);
            }
            *(float4*)&Bh[bk][bn]      = make_float4(h0[0], h0[1], h0[2], h0[3]);
            *(float4*)&Bl[bk][bn]      = make_float4(l0[0], l0[1], l0[2], l0[3]);
            *(float4*)&Bh[bk][64 + bn] = make_float4(h1[0], h1[1], h1[2], h1[3]);
            *(float4*)&Bl[bk][64 + bn] = make_float4(l1[0], l1[1], l1[2], l1[3]);
        }
        __syncthreads();

#pragma unroll
        for (int ks = 0; ks < 2; ks++) {
            const int kb = ks * 8;
            // B fragments for all 4 n-tiles
            unsigned int bh[4][2], bl[4][2];
#pragma unroll
            for (int ni = 0; ni < 4; ni++) {
                const int col = wn + ni * 8 + g;
                bh[ni][0] = __float_as_uint(Bh[kb + tg][col]);
                bh[ni][1] = __float_as_uint(Bh[kb + tg + 4][col]);
                bl[ni][0] = __float_as_uint(Bl[kb + tg][col]);
                bl[ni][1] = __float_as_uint(Bl[kb + tg + 4][col]);
            }
#pragma unroll
            for (int mi = 0; mi < 4; mi++) {
                const int row = wm + mi * 16 + g;
                unsigned int ah[4], al[4];
                ah[0] = __float_as_uint(Ah[kb + tg][row]);
                ah[1] = __float_as_uint(Ah[kb + tg][row + 8]);
                ah[2] = __float_as_uint(Ah[kb + tg + 4][row]);
                ah[3] = __float_as_uint(Ah[kb + tg + 4][row + 8]);
                al[0] = __float_as_uint(Al[kb + tg][row]);
                al[1] = __float_as_uint(Al[kb + tg][row + 8]);
                al[2] = __float_as_uint(Al[kb + tg + 4][row]);
                al[3] = __float_as_uint(Al[kb + tg + 4][row + 8]);
#pragma unroll
                for (int ni = 0; ni < 4; ni++) {
                    mma_tf32(acc[mi][ni], ah, bh[ni]);
                    mma_tf32(acc[mi][ni], ah, bl[ni]);
                    mma_tf32(acc[mi][ni], al, bh[ni]);
                }
            }
        }
    }

    // epilogue: c0,c1 -> (row, 2tg), (row, 2tg+1); c2,c3 -> row+8
#pragma unroll
    for (int mi = 0; mi < 4; mi++) {
        const int row = m0 + wm + mi * 16 + g;
#pragma unroll
        for (int ni = 0; ni < 4; ni++) {
            const int col = n0 + wn + ni * 8 + tg * 2;
            *(float2*)&C[(long long)row * N + col] =
                make_float2(acc[mi][ni][0], acc[mi][ni][1]);
            *(float2*)&C[(long long)(row + 8) * N + col] =
                make_float2(acc[mi][ni][2], acc[mi][ni][3]);
        }
    }
}

// ---------------- generic tiled SGEMM: C = A[MxK] * B[KxN] ------------------
__global__ __launch_bounds__(256) void sgemm128(
    const float* __restrict__ A, const float* __restrict__ Bm,
    float* __restrict__ C, int M, int N, int K,
    long long sA, long long sB, long long sC)
{
    A  += (long long)blockIdx.z * sA;
    Bm += (long long)blockIdx.z * sB;
    C  += (long long)blockIdx.z * sC;

    __shared__ float As[8][132];
    __shared__ float Bs[8][132];

    const int t  = threadIdx.x;
    const int tx = t % 16;
    const int ty = t / 16;
    const int m0 = blockIdx.y * 128;
    const int n0 = blockIdx.x * 128;

    float acc[8][8];
#pragma unroll
    for (int i = 0; i < 8; i++)
#pragma unroll
        for (int j = 0; j < 8; j++) acc[i][j] = 0.f;

    for (int k0 = 0; k0 < K; k0 += 8) {
#pragma unroll
        for (int p = 0; p < 4; p++) {
            int idx = t + 256 * p;
            int m = idx >> 3, k = idx & 7;
            int gm = m0 + m;
            As[k][m] = (gm < M) ? A[(long long)gm * K + (k0 + k)] : 0.f;
        }
#pragma unroll
        for (int p = 0; p < 4; p++) {
            int idx = t + 256 * p;
            int k = idx >> 7, n = idx & 127;
            int gn = n0 + n;
            Bs[k][n] = (gn < N) ? Bm[(long long)(k0 + k) * N + gn] : 0.f;
        }
        __syncthreads();

#pragma unroll
        for (int kk = 0; kk < 8; kk++) {
            float a[8], b[8];
#pragma unroll
            for (int i = 0; i < 4; i++) {
                a[i]     = As[kk][ty * 4 + i];
                a[4 + i] = As[kk][64 + ty * 4 + i];
            }
#pragma unroll
            for (int j = 0; j < 4; j++) {
                b[j]     = Bs[kk][tx * 4 + j];
                b[4 + j] = Bs[kk][64 + tx * 4 + j];
            }
#pragma unroll
            for (int i = 0; i < 8; i++)
#pragma unroll
                for (int j = 0; j < 8; j++)
                    acc[i][j] += a[i] * b[j];
        }
        __syncthreads();
    }

#pragma unroll
    for (int i = 0; i < 8; i++) {
        int gm = m0 + ((i < 4) ? (ty * 4 + i) : (64 + ty * 4 + (i - 4)));
        if (gm >= M) continue;
#pragma unroll
        for (int j = 0; j < 8; j++) {
            int gn = n0 + ((j < 4) ? (tx * 4 + j) : (64 + tx * 4 + (j - 4)));
            if (gn < N) C[(long long)gm * N + gn] = acc[i][j];
        }
    }
}

// ---------------- pass A: per-(b,h,row) online softmax stats ----------------
// 128q x 128k tiles, 8q x 8k per thread (strided). LPT remap: longest first.
#define PA_LD 68
__global__ __launch_bounds__(256) void pass_a()
{
    extern __shared__ float sm[];
    float* Qs = sm;                    // [128][68]
    float* Ks = sm + 128 * PA_LD;      // [128][68]

    const int i0 = (15 - blockIdx.x) * 128;   // descending work size
    const int h  = blockIdx.y;
    const int b  = blockIdx.z;
    const int t  = threadIdx.x;
    const int tx = t & 15;             // k group
    const int ty = t >> 4;             // q group

    const float* Qbase = g_Q + ((long long)(b * T_ + i0)) * DM + h * DH;
    const float* Kbase = g_K + ((long long)(b * T_)) * DM + h * DH;

#pragma unroll
    for (int p = 0; p < 8; p++) {
        int idx = t + 256 * p;
        int rr = idx >> 4, dq = (idx & 15) * 4;
        *(float4*)&Qs[rr * PA_LD + dq] =
            *(const float4*)&Qbase[(long long)rr * DM + dq];
    }

    float m_run[8], l_run[8];
#pragma unroll
    for (int v = 0; v < 8; v++) { m_run[v] = -INFINITY; l_run[v] = 0.f; }

    for (int jt = 0; jt <= i0; jt += 128) {
        __syncthreads();
#pragma unroll
        for (int p = 0; p < 8; p++) {
            int idx = t + 256 * p;
            int rr = idx >> 4, dq = (idx & 15) * 4;
            *(float4*)&Ks[rr * PA_LD + dq] =
                *(const float4*)&Kbase[(long long)(jt + rr) * DM + dq];
        }
        __syncthreads();

        float s[8][8];
#pragma unroll
        for (int v = 0; v < 8; v++)
#pragma unroll
            for (int u = 0; u < 8; u++) s[v][u] = 0.f;

        const float* kp = &Ks[tx * PA_LD];
        const float* qp = &Qs[ty * PA_LD];
#pragma unroll 2
        for (int d = 0; d < 64; d += 4) {
            float4 kv[8];
#pragma unroll
            for (int u = 0; u < 8; u++)
                kv[u] = *(const float4*)&kp[u * 16 * PA_LD + d];
#pragma unroll
            for (int v = 0; v < 8; v++) {
                float4 qv = *(const float4*)&qp[v * 16 * PA_LD + d];
#pragma unroll
                for (int u = 0; u < 8; u++) {
                    s[v][u] += qv.x * kv[u].x;
                    s[v][u] += qv.y * kv[u].y;
                    s[v][u] += qv.z * kv[u].z;
                    s[v][u] += qv.w * kv[u].w;
                }
            }
        }

        const bool diag = (jt == i0);
#pragma unroll
        for (int v = 0; v < 8; v++) {
            const int i = i0 + ty + 16 * v;
            float tmax = -INFINITY;
#pragma unroll
            for (int u = 0; u < 8; u++) {
                float sv = s[v][u] * 0.125f;
                if (diag && (jt + tx + 16 * u) > i) sv = -INFINITY;
                s[v][u] = sv;
                tmax = fmaxf(tmax, sv);
            }
#pragma unroll
            for (int o = 1; o < 16; o <<= 1)
                tmax = fmaxf(tmax, __shfl_xor_sync(0xffffffffu, tmax, o));

            float nm = fmaxf(m_run[v], tmax);
            float ps = 0.f;
#pragma unroll
            for (int u = 0; u < 8; u++) ps += __expf(s[v][u] - nm);
#pragma unroll
            for (int o = 1; o < 16; o <<= 1)
                ps += __shfl_xor_sync(0xffffffffu, ps, o);
            l_run[v] = l_run[v] * __expf(m_run[v] - nm) + ps;
            m_run[v] = nm;
        }
    }

    if (tx == 0) {
#pragma unroll
        for (int v = 0; v < 8; v++) {
            int i = i0 + ty + 16 * v;
            g_m[(b * H_ + h) * T_ + i] = m_run[v];
            g_l[(b * H_ + h) * T_ + i] = l_run[v];
        }
    }
}

// ---------------- pass B: head-averaged attention matrix --------------------
// 128q x 64k tiles, 8q x 4k per thread, loop 16 heads. Dynamic smem.
__global__ __launch_bounds__(256) void pass_b(float* __restrict__ attn)
{
    extern __shared__ float sm[];
    float* Qs = sm;                          // [128][68]
    float* Ks = sm + 128 * PA_LD;            // [64][68]
    float* ms = sm + 192 * PA_LD;            // [16][128]
    float* cs = ms + 16 * 128;               // [16][128]

    const int j0 = blockIdx.x * 64;
    const int i0 = blockIdx.y * 128;
    const int b  = blockIdx.z;
    const int t  = threadIdx.x;
    const int tx = t & 15;                   // k group
    const int ty = t >> 4;                   // q group

    if (j0 > i0 + 127) {                     // fully above diagonal: zeros
#pragma unroll
        for (int p = 0; p < 8; p++) {
            int idx = t + 256 * p;
            int rr = idx >> 4, c = (idx & 15) * 4;
            float4 z = make_float4(0.f, 0.f, 0.f, 0.f);
            *(float4*)&attn[((long long)(b * T_ + i0 + rr)) * T_ + j0 + c] = z;
        }
        return;
    }

    // preload softmax stats for this i-block, all heads
    for (int p = t; p < H_ * 128; p += 256) {
        int hh = p >> 7, rr = p & 127;
        ms[p] = g_m[(b * H_ + hh) * T_ + i0 + rr];
        cs[p] = 1.f / (16.f * g_l[(b * H_ + hh) * T_ + i0 + rr]);
    }

    const bool need_mask = (j0 + 63 > i0);

    float a[8][4];
#pragma unroll
    for (int v = 0; v < 8; v++)
#pragma unroll
        for (int u = 0; u < 4; u++) a[v][u] = 0.f;

    for (int h = 0; h < H_; h++) {
        __syncthreads();
        const float* Qbase = g_Q + ((long long)(b * T_ + i0)) * DM + h * DH;
        const float* Kbase = g_K + ((long long)(b * T_ + j0)) * DM + h * DH;
#pragma unroll
        for (int p = 0; p < 8; p++) {
            int idx = t + 256 * p;
            int rr = idx >> 4, dq = (idx & 15) * 4;
            *(float4*)&Qs[rr * PA_LD + dq] =
                *(const float4*)&Qbase[(long long)rr * DM + dq];
        }
#pragma unroll
        for (int p = 0; p < 4; p++) {
            int idx = t + 256 * p;
            int rr = idx >> 4, dq = (idx & 15) * 4;
            *(float4*)&Ks[rr * PA_LD + dq] =
                *(const float4*)&Kbase[(long long)rr * DM + dq];
        }
        __syncthreads();

        float s[8][4];
#pragma unroll
        for (int v = 0; v < 8; v++)
#pragma unroll
            for (int u = 0; u < 4; u++) s[v][u] = 0.f;

        const float* kp = &Ks[tx * PA_LD];
        const float* qp = &Qs[ty * PA_LD];
#pragma unroll 2
        for (int d = 0; d < 64; d += 4) {
            float4 kv[4];
#pragma unroll
            for (int u = 0; u < 4; u++)
                kv[u] = *(const float4*)&kp[u * 16 * PA_LD + d];
#pragma unroll
            for (int v = 0; v < 8; v++) {
                float4 qv = *(const float4*)&qp[v * 16 * PA_LD + d];
#pragma unroll
                for (int u = 0; u < 4; u++) {
                    s[v][u] += qv.x * kv[u].x;
                    s[v][u] += qv.y * kv[u].y;
                    s[v][u] += qv.z * kv[u].z;
                    s[v][u] += qv.w * kv[u].w;
                }
            }
        }

#pragma unroll
        for (int v = 0; v < 8; v++) {
            const int i  = i0 + ty + 16 * v;
            const float mh   = ms[h * 128 + ty + 16 * v];
            const float coef = cs[h * 128 + ty + 16 * v];
            if (need_mask) {
#pragma unroll
                for (int u = 0; u < 4; u++) {
                    int j = j0 + tx + 16 * u;
                    if (j <= i)
                        a[v][u] += __expf(s[v][u] * 0.125f - mh) * coef;
                }
            } else {
#pragma unroll
                for (int u = 0; u < 4; u++)
                    a[v][u] += __expf(s[v][u] * 0.125f - mh) * coef;
            }
        }
    }

#pragma unroll
    for (int v = 0; v < 8; v++) {
        const int i = i0 + ty + 16 * v;
        float* orow = attn + ((long long)(b * T_ + i)) * T_;
#pragma unroll
        for (int u = 0; u < 4; u++)
            orow[j0 + tx + 16 * u] = a[v][u];
    }
}

// ---------------- launch ----------------------------------------------------
extern "C" void kernel_launch(void* const* d_in, const int* in_sizes, int n_in,
                              void* d_out, int out_size)
{
    const float* q  = (const float*)d_in[0];
    const float* k  = (const float*)d_in[1];
    const float* v  = (const float*)d_in[2];
    // d_in[3] = mask (tril) — causality applied analytically
    const float* Wq = (const float*)d_in[4];
    const float* Wk = (const float*)d_in[5];
    const float* Wv = (const float*)d_in[6];
    const float* Wo = (const float*)d_in[7];

    float* out  = (float*)d_out;
    float* attn = out + (long long)BT * DM;

    float *Qp, *Kp, *Vp, *O1p;
    cudaGetSymbolAddress((void**)&Qp,  g_Q);
    cudaGetSymbolAddress((void**)&Kp,  g_K);
    cudaGetSymbolAddress((void**)&Vp,  g_Vs);
    cudaGetSymbolAddress((void**)&O1p, g_o1);

    const int smem_a = 2 * 128 * PA_LD * 4;                       // 69632
    const int smem_b = (192 * PA_LD + 2 * 16 * 128) * 4;          // 68608
    static bool attr_set = false;
    if (!attr_set) {
        cudaFuncSetAttribute(pass_a, cudaFuncAttributeMaxDynamicSharedMemorySize, smem_a);
        cudaFuncSetAttribute(pass_b, cudaFuncAttributeMaxDynamicSharedMemorySize, smem_b);
        attr_set = true;
    }

    // 1: fused Q and K projections on tensor cores (split-tf32)
    mmproj<<<dim3(DM / 128, BT / 128, 2), 256>>>(q, Wq, Qp, k, Wk, Kp);

    // 2: V projection
    sgemm128<<<dim3(1, BT / 128, 1), 256>>>(v, Wv, Vp, BT, DH, DM, 0, 0, 0);

    // 3: softmax stats
    pass_a<<<dim3(T_ / 128, H_, B_), 256, smem_a>>>();

    // 4: head-averaged attention matrix
    pass_b<<<dim3(T_ / 64, T_ / 128, B_), 256, smem_b>>>(attn);

    // 5: out1 = attn_avg @ V_shared
    sgemm128<<<dim3(1, T_ / 128, B_), 256>>>(attn, Vp, O1p, T_, DH, T_,
                                             (long long)T_ * T_,
                                             (long long)T_ * DH,
                                             (long long)T_ * DH);

    // 6: out = out1 @ Wo
    sgemm128<<<dim3(DM / 128, BT / 128, 1), 256>>>(O1p, Wo, out, BT, DM, DH, 0, 0, 0);
}

// round 11
// speedup vs baseline: 1.4109x; 1.1039x over previous
#include <cuda_runtime.h>
#include <cuda_bf16.h>
#include <cstdint>
#include <stdint.h>
#include <math.h>

#define B_  2
#define T_  2048
#define DM  1024
#define H_  16
#define DH  64
#define BT  (B_ * T_)   // 4096

// ---------------- scratch (static device globals; no runtime alloc) ----------
__device__ float g_Q[(long long)BT * DM];     // 16.8 MB
__device__ float g_K[(long long)BT * DM];     // 16.8 MB
__device__ float g_Vs[(long long)BT * DH];    // 1 MB
__device__ float g_m[B_ * H_ * T_];
__device__ float g_l[B_ * H_ * T_];
__device__ float g_o1[(long long)BT * DH];    // 1 MB

// ---------------- bf16 split helpers ----------------------------------------
// pack two floats to bf16x2: lo_elem -> bits[0:16), hi_elem -> bits[16:32)
__device__ __forceinline__ unsigned int bf16pair(float lo_elem, float hi_elem) {
    unsigned int r;
    asm("cvt.rn.bf16x2.f32 %0, %1, %2;" : "=r"(r) : "f"(hi_elem), "f"(lo_elem));
    return r;
}

// split (x0, x1) into hi-pair and lo-pair (Markidis decomposition)
__device__ __forceinline__ void split_pair(float x0, float x1,
                                           unsigned int& hp, unsigned int& lp) {
    hp = bf16pair(x0, x1);
    float h0 = __uint_as_float(hp << 16);
    float h1 = __uint_as_float(hp & 0xFFFF0000u);
    lp = bf16pair(x0 - h0, x1 - h1);
}

__device__ __forceinline__ void mma_bf16(float* c, const unsigned int* a,
                                         const unsigned int* b) {
    asm volatile(
        "mma.sync.aligned.m16n8k16.row.col.f32.bf16.bf16.f32 "
        "{%0,%1,%2,%3}, {%4,%5,%6,%7}, {%8,%9}, {%0,%1,%2,%3};"
        : "+f"(c[0]), "+f"(c[1]), "+f"(c[2]), "+f"(c[3])
        : "r"(a[0]), "r"(a[1]), "r"(a[2]), "r"(a[3]),
          "r"(b[0]), "r"(b[1]));
}

// ---------------- split-bf16 projection GEMM --------------------------------
// C[4096x1024] = A[4096x1024] @ B[1024x1024].  blockIdx.z selects (A,B,C) set.
// 128x128 block tile, BK=16, 256 threads (8 warps, 2m x 4n), 64x32 warp tile.
// 3-term split-bf16: AhBh + AhBl + AlBh (error ~2^-16 relative).
// smem: packed bf16x2 along k: [k2][m] with row stride 136 words.
#define MM_LDP 136
__global__ __launch_bounds__(256, 2) void mmproj(
    const float* __restrict__ A,  const float* __restrict__ Bm,  float* __restrict__ C,
    const float* __restrict__ A2, const float* __restrict__ B2,  float* __restrict__ C2)
{
    if (blockIdx.z == 1) { A = A2; Bm = B2; C = C2; }
    const int K = DM, N = DM;

    __shared__ unsigned int Aph[8][MM_LDP], Apl[8][MM_LDP];
    __shared__ unsigned int Bph[8][MM_LDP], Bpl[8][MM_LDP];

    const int t    = threadIdx.x;
    const int wid  = t >> 5;
    const int lane = t & 31;
    const int g    = lane >> 2;       // group id (0..7)
    const int tq   = lane & 3;        // thread-in-group
    const int wm   = (wid >> 2) * 64; // warp m offset
    const int wn   = (wid & 3) * 32;  // warp n offset
    const int m0   = blockIdx.y * 128;
    const int n0   = blockIdx.x * 128;

    float acc[4][4][4];
#pragma unroll
    for (int mi = 0; mi < 4; mi++)
#pragma unroll
        for (int ni = 0; ni < 4; ni++)
#pragma unroll
            for (int e = 0; e < 4; e++) acc[mi][ni][e] = 0.f;

    // A load coords: row am, k block of 8 (two float4)
    const int am   = t & 127;
    const int ak   = (t >> 7) * 8;    // k offset 0 or 8
    const int ak2  = ak >> 1;         // pair row 0 or 4
    // B load coords: k-row pair (2rp, 2rp+1), 4 cols
    const int rp   = t >> 5;          // 0..7
    const int bc   = (t & 31) * 4;    // col offset (0..124)

    for (int k0 = 0; k0 < K; k0 += 16) {
        // global loads first (latency overlap with previous tile's MMAs)
        float4 av0 = *(const float4*)&A [(long long)(m0 + am) * K + k0 + ak];
        float4 av1 = *(const float4*)&A [(long long)(m0 + am) * K + k0 + ak + 4];
        float4 bv0 = *(const float4*)&Bm[(long long)(k0 + 2 * rp)     * N + n0 + bc];
        float4 bv1 = *(const float4*)&Bm[(long long)(k0 + 2 * rp + 1) * N + n0 + bc];

        __syncthreads();   // previous tile fully consumed

        // A: pack k-pairs (consecutive k within the thread's 8 values)
        {
            float va[8] = {av0.x, av0.y, av0.z, av0.w, av1.x, av1.y, av1.z, av1.w};
#pragma unroll
            for (int i = 0; i < 4; i++) {
                unsigned int hp, lp;
                split_pair(va[2 * i], va[2 * i + 1], hp, lp);
                Aph[ak2 + i][am] = hp;
                Apl[ak2 + i][am] = lp;
            }
        }
        // B: pack k-pairs across the two loaded rows, per column
        {
            float r0[4] = {bv0.x, bv0.y, bv0.z, bv0.w};
            float r1[4] = {bv1.x, bv1.y, bv1.z, bv1.w};
#pragma unroll
            for (int c = 0; c < 4; c++) {
                unsigned int hp, lp;
                split_pair(r0[c], r1[c], hp, lp);   // lower = even k
                Bph[rp][bc + c] = hp;
                Bpl[rp][bc + c] = lp;
            }
        }
        __syncthreads();

        // fragments: a0=(g,2tq..), a1=(g+8,..), a2=(g,2tq+8..), a3=(g+8,..)
        unsigned int bh[4][2], bl[4][2];
#pragma unroll
        for (int ni = 0; ni < 4; ni++) {
            const int col = wn + ni * 8 + g;
            bh[ni][0] = Bph[tq][col];
            bh[ni][1] = Bph[tq + 4][col];
            bl[ni][0] = Bpl[tq][col];
            bl[ni][1] = Bpl[tq + 4][col];
        }
#pragma unroll
        for (int mi = 0; mi < 4; mi++) {
            const int row = wm + mi * 16 + g;
            unsigned int ah[4], al[4];
            ah[0] = Aph[tq][row];
            ah[1] = Aph[tq][row + 8];
            ah[2] = Aph[tq + 4][row];
            ah[3] = Aph[tq + 4][row + 8];
            al[0] = Apl[tq][row];
            al[1] = Apl[tq][row + 8];
            al[2] = Apl[tq + 4][row];
            al[3] = Apl[tq + 4][row + 8];
#pragma unroll
            for (int ni = 0; ni < 4; ni++) {
                mma_bf16(acc[mi][ni], ah, bh[ni]);
                mma_bf16(acc[mi][ni], ah, bl[ni]);
                mma_bf16(acc[mi][ni], al, bh[ni]);
            }
        }
    }

    // epilogue: c0,c1 -> (row, 2tq), (row, 2tq+1); c2,c3 -> row+8
#pragma unroll
    for (int mi = 0; mi < 4; mi++) {
        const int row = m0 + wm + mi * 16 + g;
#pragma unroll
        for (int ni = 0; ni < 4; ni++) {
            const int col = n0 + wn + ni * 8 + tq * 2;
            *(float2*)&C[(long long)row * N + col] =
                make_float2(acc[mi][ni][0], acc[mi][ni][1]);
            *(float2*)&C[(long long)(row + 8) * N + col] =
                make_float2(acc[mi][ni][2], acc[mi][ni][3]);
        }
    }
}

// ---------------- generic tiled SGEMM: C = A[MxK] * B[KxN] ------------------
__global__ __launch_bounds__(256) void sgemm128(
    const float* __restrict__ A, const float* __restrict__ Bm,
    float* __restrict__ C, int M, int N, int K,
    long long sA, long long sB, long long sC)
{
    A  += (long long)blockIdx.z * sA;
    Bm += (long long)blockIdx.z * sB;
    C  += (long long)blockIdx.z * sC;

    __shared__ float As[8][132];
    __shared__ float Bs[8][132];

    const int t  = threadIdx.x;
    const int tx = t % 16;
    const int ty = t / 16;
    const int m0 = blockIdx.y * 128;
    const int n0 = blockIdx.x * 128;

    float acc[8][8];
#pragma unroll
    for (int i = 0; i < 8; i++)
#pragma unroll
        for (int j = 0; j < 8; j++) acc[i][j] = 0.f;

    for (int k0 = 0; k0 < K; k0 += 8) {
#pragma unroll
        for (int p = 0; p < 4; p++) {
            int idx = t + 256 * p;
            int m = idx >> 3, k = idx & 7;
            int gm = m0 + m;
            As[k][m] = (gm < M) ? A[(long long)gm * K + (k0 + k)] : 0.f;
        }
#pragma unroll
        for (int p = 0; p < 4; p++) {
            int idx = t + 256 * p;
            int k = idx >> 7, n = idx & 127;
            int gn = n0 + n;
            Bs[k][n] = (gn < N) ? Bm[(long long)(k0 + k) * N + gn] : 0.f;
        }
        __syncthreads();

#pragma unroll
        for (int kk = 0; kk < 8; kk++) {
            float a[8], b[8];
#pragma unroll
            for (int i = 0; i < 4; i++) {
                a[i]     = As[kk][ty * 4 + i];
                a[4 + i] = As[kk][64 + ty * 4 + i];
            }
#pragma unroll
            for (int j = 0; j < 4; j++) {
                b[j]     = Bs[kk][tx * 4 + j];
                b[4 + j] = Bs[kk][64 + tx * 4 + j];
            }
#pragma unroll
            for (int i = 0; i < 8; i++)
#pragma unroll
                for (int j = 0; j < 8; j++)
                    acc[i][j] += a[i] * b[j];
        }
        __syncthreads();
    }

#pragma unroll
    for (int i = 0; i < 8; i++) {
        int gm = m0 + ((i < 4) ? (ty * 4 + i) : (64 + ty * 4 + (i - 4)));
        if (gm >= M) continue;
#pragma unroll
        for (int j = 0; j < 8; j++) {
            int gn = n0 + ((j < 4) ? (tx * 4 + j) : (64 + tx * 4 + (j - 4)));
            if (gn < N) C[(long long)gm * N + gn] = acc[i][j];
        }
    }
}

// ---------------- pass A: per-(b,h,row) online softmax stats ----------------
// 128q x 128k tiles, 8q x 8k per thread (strided). LPT remap: longest first.
#define PA_LD 68
__global__ __launch_bounds__(256) void pass_a()
{
    extern __shared__ float sm[];
    float* Qs = sm;                    // [128][68]
    float* Ks = sm + 128 * PA_LD;      // [128][68]

    const int i0 = (15 - blockIdx.x) * 128;   // descending work size
    const int h  = blockIdx.y;
    const int b  = blockIdx.z;
    const int t  = threadIdx.x;
    const int tx = t & 15;             // k group
    const int ty = t >> 4;             // q group

    const float* Qbase = g_Q + ((long long)(b * T_ + i0)) * DM + h * DH;
    const float* Kbase = g_K + ((long long)(b * T_)) * DM + h * DH;

#pragma unroll
    for (int p = 0; p < 8; p++) {
        int idx = t + 256 * p;
        int rr = idx >> 4, dq = (idx & 15) * 4;
        *(float4*)&Qs[rr * PA_LD + dq] =
            *(const float4*)&Qbase[(long long)rr * DM + dq];
    }

    float m_run[8], l_run[8];
#pragma unroll
    for (int v = 0; v < 8; v++) { m_run[v] = -INFINITY; l_run[v] = 0.f; }

    for (int jt = 0; jt <= i0; jt += 128) {
        __syncthreads();
#pragma unroll
        for (int p = 0; p < 8; p++) {
            int idx = t + 256 * p;
            int rr = idx >> 4, dq = (idx & 15) * 4;
            *(float4*)&Ks[rr * PA_LD + dq] =
                *(const float4*)&Kbase[(long long)(jt + rr) * DM + dq];
        }
        __syncthreads();

        float s[8][8];
#pragma unroll
        for (int v = 0; v < 8; v++)
#pragma unroll
            for (int u = 0; u < 8; u++) s[v][u] = 0.f;

        const float* kp = &Ks[tx * PA_LD];
        const float* qp = &Qs[ty * PA_LD];
#pragma unroll 2
        for (int d = 0; d < 64; d += 4) {
            float4 kv[8];
#pragma unroll
            for (int u = 0; u < 8; u++)
                kv[u] = *(const float4*)&kp[u * 16 * PA_LD + d];
#pragma unroll
            for (int v = 0; v < 8; v++) {
                float4 qv = *(const float4*)&qp[v * 16 * PA_LD + d];
#pragma unroll
                for (int u = 0; u < 8; u++) {
                    s[v][u] += qv.x * kv[u].x;
                    s[v][u] += qv.y * kv[u].y;
                    s[v][u] += qv.z * kv[u].z;
                    s[v][u] += qv.w * kv[u].w;
                }
            }
        }

        const bool diag = (jt == i0);
#pragma unroll
        for (int v = 0; v < 8; v++) {
            const int i = i0 + ty + 16 * v;
            float tmax = -INFINITY;
#pragma unroll
            for (int u = 0; u < 8; u++) {
                float sv = s[v][u] * 0.125f;
                if (diag && (jt + tx + 16 * u) > i) sv = -INFINITY;
                s[v][u] = sv;
                tmax = fmaxf(tmax, sv);
            }
#pragma unroll
            for (int o = 1; o < 16; o <<= 1)
                tmax = fmaxf(tmax, __shfl_xor_sync(0xffffffffu, tmax, o));

            float nm = fmaxf(m_run[v], tmax);
            float ps = 0.f;
#pragma unroll
            for (int u = 0; u < 8; u++) ps += __expf(s[v][u] - nm);
#pragma unroll
            for (int o = 1; o < 16; o <<= 1)
                ps += __shfl_xor_sync(0xffffffffu, ps, o);
            l_run[v] = l_run[v] * __expf(m_run[v] - nm) + ps;
            m_run[v] = nm;
        }
    }

    if (tx == 0) {
#pragma unroll
        for (int v = 0; v < 8; v++) {
            int i = i0 + ty + 16 * v;
            g_m[(b * H_ + h) * T_ + i] = m_run[v];
            g_l[(b * H_ + h) * T_ + i] = l_run[v];
        }
    }
}

// ---------------- pass B: head-averaged attention matrix --------------------
// 128q x 64k tiles, 8q x 4k per thread, loop 16 heads. Dynamic smem.
__global__ __launch_bounds__(256) void pass_b(float* __restrict__ attn)
{
    extern __shared__ float sm[];
    float* Qs = sm;                          // [128][68]
    float* Ks = sm + 128 * PA_LD;            // [64][68]
    float* ms = sm + 192 * PA_LD;            // [16][128]
    float* cs = ms + 16 * 128;               // [16][128]

    const int j0 = blockIdx.x * 64;
    const int i0 = blockIdx.y * 128;
    const int b  = blockIdx.z;
    const int t  = threadIdx.x;
    const int tx = t & 15;                   // k group
    const int ty = t >> 4;                   // q group

    if (j0 > i0 + 127) {                     // fully above diagonal: zeros
#pragma unroll
        for (int p = 0; p < 8; p++) {
            int idx = t + 256 * p;
            int rr = idx >> 4, c = (idx & 15) * 4;
            float4 z = make_float4(0.f, 0.f, 0.f, 0.f);
            *(float4*)&attn[((long long)(b * T_ + i0 + rr)) * T_ + j0 + c] = z;
        }
        return;
    }

    // preload softmax stats for this i-block, all heads
    for (int p = t; p < H_ * 128; p += 256) {
        int hh = p >> 7, rr = p & 127;
        ms[p] = g_m[(b * H_ + hh) * T_ + i0 + rr];
        cs[p] = 1.f / (16.f * g_l[(b * H_ + hh) * T_ + i0 + rr]);
    }

    const bool need_mask = (j0 + 63 > i0);

    float a[8][4];
#pragma unroll
    for (int v = 0; v < 8; v++)
#pragma unroll
        for (int u = 0; u < 4; u++) a[v][u] = 0.f;

    for (int h = 0; h < H_; h++) {
        __syncthreads();
        const float* Qbase = g_Q + ((long long)(b * T_ + i0)) * DM + h * DH;
        const float* Kbase = g_K + ((long long)(b * T_ + j0)) * DM + h * DH;
#pragma unroll
        for (int p = 0; p < 8; p++) {
            int idx = t + 256 * p;
            int rr = idx >> 4, dq = (idx & 15) * 4;
            *(float4*)&Qs[rr * PA_LD + dq] =
                *(const float4*)&Qbase[(long long)rr * DM + dq];
        }
#pragma unroll
        for (int p = 0; p < 4; p++) {
            int idx = t + 256 * p;
            int rr = idx >> 4, dq = (idx & 15) * 4;
            *(float4*)&Ks[rr * PA_LD + dq] =
                *(const float4*)&Kbase[(long long)rr * DM + dq];
        }
        __syncthreads();

        float s[8][4];
#pragma unroll
        for (int v = 0; v < 8; v++)
#pragma unroll
            for (int u = 0; u < 4; u++) s[v][u] = 0.f;

        const float* kp = &Ks[tx * PA_LD];
        const float* qp = &Qs[ty * PA_LD];
#pragma unroll 2
        for (int d = 0; d < 64; d += 4) {
            float4 kv[4];
#pragma unroll
            for (int u = 0; u < 4; u++)
                kv[u] = *(const float4*)&kp[u * 16 * PA_LD + d];
#pragma unroll
            for (int v = 0; v < 8; v++) {
                float4 qv = *(const float4*)&qp[v * 16 * PA_LD + d];
#pragma unroll
                for (int u = 0; u < 4; u++) {
                    s[v][u] += qv.x * kv[u].x;
                    s[v][u] += qv.y * kv[u].y;
                    s[v][u] += qv.z * kv[u].z;
                    s[v][u] += qv.w * kv[u].w;
                }
            }
        }

#pragma unroll
        for (int v = 0; v < 8; v++) {
            const int i  = i0 + ty + 16 * v;
            const float mh   = ms[h * 128 + ty + 16 * v];
            const float coef = cs[h * 128 + ty + 16 * v];
            if (need_mask) {
#pragma unroll
                for (int u = 0; u < 4; u++) {
                    int j = j0 + tx + 16 * u;
                    if (j <= i)
                        a[v][u] += __expf(s[v][u] * 0.125f - mh) * coef;
                }
            } else {
#pragma unroll
                for (int u = 0; u < 4; u++)
                    a[v][u] += __expf(s[v][u] * 0.125f - mh) * coef;
            }
        }
    }

#pragma unroll
    for (int v = 0; v < 8; v++) {
        const int i = i0 + ty + 16 * v;
        float* orow = attn + ((long long)(b * T_ + i)) * T_;
#pragma unroll
        for (int u = 0; u < 4; u++)
            orow[j0 + tx + 16 * u] = a[v][u];
    }
}

// ---------------- launch ----------------------------------------------------
extern "C" void kernel_launch(void* const* d_in, const int* in_sizes, int n_in,
                              void* d_out, int out_size)
{
    const float* q  = (const float*)d_in[0];
    const float* k  = (const float*)d_in[1];
    const float* v  = (const float*)d_in[2];
    // d_in[3] = mask (tril) — causality applied analytically
    const float* Wq = (const float*)d_in[4];
    const float* Wk = (const float*)d_in[5];
    const float* Wv = (const float*)d_in[6];
    const float* Wo = (const float*)d_in[7];

    float* out  = (float*)d_out;
    float* attn = out + (long long)BT * DM;

    float *Qp, *Kp, *Vp, *O1p;
    cudaGetSymbolAddress((void**)&Qp,  g_Q);
    cudaGetSymbolAddress((void**)&Kp,  g_K);
    cudaGetSymbolAddress((void**)&Vp,  g_Vs);
    cudaGetSymbolAddress((void**)&O1p, g_o1);

    const int smem_a = 2 * 128 * PA_LD * 4;                       // 69632
    const int smem_b = (192 * PA_LD + 2 * 16 * 128) * 4;          // 68608
    static bool attr_set = false;
    if (!attr_set) {
        cudaFuncSetAttribute(pass_a, cudaFuncAttributeMaxDynamicSharedMemorySize, smem_a);
        cudaFuncSetAttribute(pass_b, cudaFuncAttributeMaxDynamicSharedMemorySize, smem_b);
        attr_set = true;
    }

    // 1: fused Q and K projections on tensor cores (split-bf16, m16n8k16)
    mmproj<<<dim3(DM / 128, BT / 128, 2), 256>>>(q, Wq, Qp, k, Wk, Kp);

    // 2: V projection
    sgemm128<<<dim3(1, BT / 128, 1), 256>>>(v, Wv, Vp, BT, DH, DM, 0, 0, 0);

    // 3: softmax stats
    pass_a<<<dim3(T_ / 128, H_, B_), 256, smem_a>>>();

    // 4: head-averaged attention matrix
    pass_b<<<dim3(T_ / 64, T_ / 128, B_), 256, smem_b>>>(attn);

    // 5: out1 = attn_avg @ V_shared
    sgemm128<<<dim3(1, T_ / 128, B_), 256>>>(attn, Vp, O1p, T_, DH, T_,
                                             (long long)T_ * T_,
                                             (long long)T_ * DH,
                                             (long long)T_ * DH);

    // 6: out = out1 @ Wo
    sgemm128<<<dim3(DM / 128, BT / 128, 1), 256>>>(O1p, Wo, out, BT, DM, DH, 0, 0, 0);
}

// round 13
// speedup vs baseline: 1.5420x; 1.0929x over previous
#include <cuda_runtime.h>
#include <cuda_bf16.h>
#include <cstdint>
#include <stdint.h>
#include <math.h>

#define B_  2
#define T_  2048
#define DM  1024
#define H_  16
#define DH  64
#define BT  (B_ * T_)   // 4096

// ---------------- scratch (static device globals; no runtime alloc) ----------
__device__ float g_Q[(long long)BT * DM];     // 16.8 MB
__device__ float g_K[(long long)BT * DM];     // 16.8 MB
__device__ float g_Vs[(long long)BT * DH];    // 1 MB
__device__ float g_m[B_ * H_ * T_];
__device__ float g_l[B_ * H_ * T_];
__device__ float g_o1[(long long)BT * DH];    // 1 MB
// packed split-bf16 Q/K: bf16x2 pairs along d, [BT][512]
__device__ unsigned int g_Qph[(long long)BT * 512];
__device__ unsigned int g_Qpl[(long long)BT * 512];
__device__ unsigned int g_Kph[(long long)BT * 512];
__device__ unsigned int g_Kpl[(long long)BT * 512];

// ---------------- zero helper -----------------------------------------------
__global__ void zero_kernel(float* p, long long n4)
{
    long long i = blockIdx.x * (long long)blockDim.x + threadIdx.x;
    long long stride = (long long)gridDim.x * blockDim.x;
    float4 z = make_float4(0.f, 0.f, 0.f, 0.f);
    for (; i < n4; i += stride)
        ((float4*)p)[i] = z;
}

// ---------------- bf16 split helpers ----------------------------------------
__device__ __forceinline__ unsigned int bf16pair(float lo_elem, float hi_elem) {
    unsigned int r;
    asm("cvt.rn.bf16x2.f32 %0, %1, %2;" : "=r"(r) : "f"(hi_elem), "f"(lo_elem));
    return r;
}

__device__ __forceinline__ void split_pair(float x0, float x1,
                                           unsigned int& hp, unsigned int& lp) {
    hp = bf16pair(x0, x1);
    float h0 = __uint_as_float(hp << 16);
    float h1 = __uint_as_float(hp & 0xFFFF0000u);
    lp = bf16pair(x0 - h0, x1 - h1);
}

__device__ __forceinline__ void mma_bf16(float* c, const unsigned int* a,
                                         const unsigned int* b) {
    asm volatile(
        "mma.sync.aligned.m16n8k16.row.col.f32.bf16.bf16.f32 "
        "{%0,%1,%2,%3}, {%4,%5,%6,%7}, {%8,%9}, {%0,%1,%2,%3};"
        : "+f"(c[0]), "+f"(c[1]), "+f"(c[2]), "+f"(c[3])
        : "r"(a[0]), "r"(a[1]), "r"(a[2]), "r"(a[3]),
          "r"(b[0]), "r"(b[1]));
}

// ---------------- split-bf16 projection GEMM + packed output ----------------
#define MM_LDP 136
__global__ __launch_bounds__(256, 2) void mmproj(
    const float* __restrict__ A,  const float* __restrict__ Bm,  float* __restrict__ C,
    const float* __restrict__ A2, const float* __restrict__ B2,  float* __restrict__ C2)
{
    unsigned int* PH = g_Qph;
    unsigned int* PL = g_Qpl;
    if (blockIdx.z == 1) { A = A2; Bm = B2; C = C2; PH = g_Kph; PL = g_Kpl; }
    const int K = DM, N = DM;

    __shared__ unsigned int Aph[8][MM_LDP], Apl[8][MM_LDP];
    __shared__ unsigned int Bph[8][MM_LDP], Bpl[8][MM_LDP];

    const int t    = threadIdx.x;
    const int wid  = t >> 5;
    const int lane = t & 31;
    const int g    = lane >> 2;
    const int tq   = lane & 3;
    const int wm   = (wid >> 2) * 64;
    const int wn   = (wid & 3) * 32;
    const int m0   = blockIdx.y * 128;
    const int n0   = blockIdx.x * 128;

    float acc[4][4][4];
#pragma unroll
    for (int mi = 0; mi < 4; mi++)
#pragma unroll
        for (int ni = 0; ni < 4; ni++)
#pragma unroll
            for (int e = 0; e < 4; e++) acc[mi][ni][e] = 0.f;

    const int am   = t & 127;
    const int ak   = (t >> 7) * 8;
    const int ak2  = ak >> 1;
    const int rp   = t >> 5;
    const int bc   = (t & 31) * 4;

    for (int k0 = 0; k0 < K; k0 += 16) {
        float4 av0 = *(const float4*)&A [(long long)(m0 + am) * K + k0 + ak];
        float4 av1 = *(const float4*)&A [(long long)(m0 + am) * K + k0 + ak + 4];
        float4 bv0 = *(const float4*)&Bm[(long long)(k0 + 2 * rp)     * N + n0 + bc];
        float4 bv1 = *(const float4*)&Bm[(long long)(k0 + 2 * rp + 1) * N + n0 + bc];

        __syncthreads();

        {
            float va[8] = {av0.x, av0.y, av0.z, av0.w, av1.x, av1.y, av1.z, av1.w};
#pragma unroll
            for (int i = 0; i < 4; i++) {
                unsigned int hp, lp;
                split_pair(va[2 * i], va[2 * i + 1], hp, lp);
                Aph[ak2 + i][am] = hp;
                Apl[ak2 + i][am] = lp;
            }
        }
        {
            float r0[4] = {bv0.x, bv0.y, bv0.z, bv0.w};
            float r1[4] = {bv1.x, bv1.y, bv1.z, bv1.w};
#pragma unroll
            for (int c = 0; c < 4; c++) {
                unsigned int hp, lp;
                split_pair(r0[c], r1[c], hp, lp);
                Bph[rp][bc + c] = hp;
                Bpl[rp][bc + c] = lp;
            }
        }
        __syncthreads();

        unsigned int bh[4][2], bl[4][2];
#pragma unroll
        for (int ni = 0; ni < 4; ni++) {
            const int col = wn + ni * 8 + g;
            bh[ni][0] = Bph[tq][col];
            bh[ni][1] = Bph[tq + 4][col];
            bl[ni][0] = Bpl[tq][col];
            bl[ni][1] = Bpl[tq + 4][col];
        }
#pragma unroll
        for (int mi = 0; mi < 4; mi++) {
            const int row = wm + mi * 16 + g;
            unsigned int ah[4], al[4];
            ah[0] = Aph[tq][row];
            ah[1] = Aph[tq][row + 8];
            ah[2] = Aph[tq + 4][row];
            ah[3] = Aph[tq + 4][row + 8];
            al[0] = Apl[tq][row];
            al[1] = Apl[tq][row + 8];
            al[2] = Apl[tq + 4][row];
            al[3] = Apl[tq + 4][row + 8];
#pragma unroll
            for (int ni = 0; ni < 4; ni++) {
                mma_bf16(acc[mi][ni], ah, bh[ni]);
                mma_bf16(acc[mi][ni], ah, bl[ni]);
                mma_bf16(acc[mi][ni], al, bh[ni]);
            }
        }
    }

    // epilogue: fp32 C + packed split-bf16 (pairs are consecutive cols)
#pragma unroll
    for (int mi = 0; mi < 4; mi++) {
        const int row = m0 + wm + mi * 16 + g;
#pragma unroll
        for (int ni = 0; ni < 4; ni++) {
            const int col = n0 + wn + ni * 8 + tq * 2;
            *(float2*)&C[(long long)row * N + col] =
                make_float2(acc[mi][ni][0], acc[mi][ni][1]);
            *(float2*)&C[(long long)(row + 8) * N + col] =
                make_float2(acc[mi][ni][2], acc[mi][ni][3]);

            const int pc = col >> 1;
            unsigned int hp, lp;
            split_pair(acc[mi][ni][0], acc[mi][ni][1], hp, lp);
            PH[(long long)row * 512 + pc] = hp;
            PL[(long long)row * 512 + pc] = lp;
            split_pair(acc[mi][ni][2], acc[mi][ni][3], hp, lp);
            PH[(long long)(row + 8) * 512 + pc] = hp;
            PL[(long long)(row + 8) * 512 + pc] = lp;
        }
    }
}

// ---------------- generic tiled SGEMM: C = A[MxK] * B[KxN] ------------------
__global__ __launch_bounds__(256) void sgemm128(
    const float* __restrict__ A, const float* __restrict__ Bm,
    float* __restrict__ C, int M, int N, int K,
    long long sA, long long sB, long long sC)
{
    A  += (long long)blockIdx.z * sA;
    Bm += (long long)blockIdx.z * sB;
    C  += (long long)blockIdx.z * sC;

    __shared__ float As[8][132];
    __shared__ float Bs[8][132];

    const int t  = threadIdx.x;
    const int tx = t % 16;
    const int ty = t / 16;
    const int m0 = blockIdx.y * 128;
    const int n0 = blockIdx.x * 128;

    float acc[8][8];
#pragma unroll
    for (int i = 0; i < 8; i++)
#pragma unroll
        for (int j = 0; j < 8; j++) acc[i][j] = 0.f;

    for (int k0 = 0; k0 < K; k0 += 8) {
#pragma unroll
        for (int p = 0; p < 4; p++) {
            int idx = t + 256 * p;
            int m = idx >> 3, k = idx & 7;
            int gm = m0 + m;
            As[k][m] = (gm < M) ? A[(long long)gm * K + (k0 + k)] : 0.f;
        }
#pragma unroll
        for (int p = 0; p < 4; p++) {
            int idx = t + 256 * p;
            int k = idx >> 7, n = idx & 127;
            int gn = n0 + n;
            Bs[k][n] = (gn < N) ? Bm[(long long)(k0 + k) * N + gn] : 0.f;
        }
        __syncthreads();

#pragma unroll
        for (int kk = 0; kk < 8; kk++) {
            float a[8], b[8];
#pragma unroll
            for (int i = 0; i < 4; i++) {
                a[i]     = As[kk][ty * 4 + i];
                a[4 + i] = As[kk][64 + ty * 4 + i];
            }
#pragma unroll
            for (int j = 0; j < 4; j++) {
                b[j]     = Bs[kk][tx * 4 + j];
                b[4 + j] = Bs[kk][64 + tx * 4 + j];
            }
#pragma unroll
            for (int i = 0; i < 8; i++)
#pragma unroll
                for (int j = 0; j < 8; j++)
                    acc[i][j] += a[i] * b[j];
        }
        __syncthreads();
    }

#pragma unroll
    for (int i = 0; i < 8; i++) {
        int gm = m0 + ((i < 4) ? (ty * 4 + i) : (64 + ty * 4 + (i - 4)));
        if (gm >= M) continue;
#pragma unroll
        for (int j = 0; j < 8; j++) {
            int gn = n0 + ((j < 4) ? (tx * 4 + j) : (64 + tx * 4 + (j - 4)));
            if (gn < N) C[(long long)gm * N + gn] = acc[i][j];
        }
    }
}

// ---------------- pass A: per-(b,h,row) online softmax stats (FFMA) ---------
#define PA_LD 68
__global__ __launch_bounds__(256) void pass_a()
{
    extern __shared__ float sm[];
    float* Qs = sm;
    float* Ks = sm + 128 * PA_LD;

    const int i0 = (15 - blockIdx.x) * 128;
    const int h  = blockIdx.y;
    const int b  = blockIdx.z;
    const int t  = threadIdx.x;
    const int tx = t & 15;
    const int ty = t >> 4;

    const float* Qbase = g_Q + ((long long)(b * T_ + i0)) * DM + h * DH;
    const float* Kbase = g_K + ((long long)(b * T_)) * DM + h * DH;

#pragma unroll
    for (int p = 0; p < 8; p++) {
        int idx = t + 256 * p;
        int rr = idx >> 4, dq = (idx & 15) * 4;
        *(float4*)&Qs[rr * PA_LD + dq] =
            *(const float4*)&Qbase[(long long)rr * DM + dq];
    }

    float m_run[8], l_run[8];
#pragma unroll
    for (int v = 0; v < 8; v++) { m_run[v] = -INFINITY; l_run[v] = 0.f; }

    for (int jt = 0; jt <= i0; jt += 128) {
        __syncthreads();
#pragma unroll
        for (int p = 0; p < 8; p++) {
            int idx = t + 256 * p;
            int rr = idx >> 4, dq = (idx & 15) * 4;
            *(float4*)&Ks[rr * PA_LD + dq] =
                *(const float4*)&Kbase[(long long)(jt + rr) * DM + dq];
        }
        __syncthreads();

        float s[8][8];
#pragma unroll
        for (int v = 0; v < 8; v++)
#pragma unroll
            for (int u = 0; u < 8; u++) s[v][u] = 0.f;

        const float* kp = &Ks[tx * PA_LD];
        const float* qp = &Qs[ty * PA_LD];
#pragma unroll 2
        for (int d = 0; d < 64; d += 4) {
            float4 kv[8];
#pragma unroll
            for (int u = 0; u < 8; u++)
                kv[u] = *(const float4*)&kp[u * 16 * PA_LD + d];
#pragma unroll
            for (int v = 0; v < 8; v++) {
                float4 qv = *(const float4*)&qp[v * 16 * PA_LD + d];
#pragma unroll
                for (int u = 0; u < 8; u++) {
                    s[v][u] += qv.x * kv[u].x;
                    s[v][u] += qv.y * kv[u].y;
                    s[v][u] += qv.z * kv[u].z;
                    s[v][u] += qv.w * kv[u].w;
                }
            }
        }

        const bool diag = (jt == i0);
#pragma unroll
        for (int v = 0; v < 8; v++) {
            const int i = i0 + ty + 16 * v;
            float tmax = -INFINITY;
#pragma unroll
            for (int u = 0; u < 8; u++) {
                float sv = s[v][u] * 0.125f;
                if (diag && (jt + tx + 16 * u) > i) sv = -INFINITY;
                s[v][u] = sv;
                tmax = fmaxf(tmax, sv);
            }
#pragma unroll
            for (int o = 1; o < 16; o <<= 1)
                tmax = fmaxf(tmax, __shfl_xor_sync(0xffffffffu, tmax, o));

            float nm = fmaxf(m_run[v], tmax);
            float ps = 0.f;
#pragma unroll
            for (int u = 0; u < 8; u++) ps += __expf(s[v][u] - nm);
#pragma unroll
            for (int o = 1; o < 16; o <<= 1)
                ps += __shfl_xor_sync(0xffffffffu, ps, o);
            l_run[v] = l_run[v] * __expf(m_run[v] - nm) + ps;
            m_run[v] = nm;
        }
    }

    if (tx == 0) {
#pragma unroll
        for (int v = 0; v < 8; v++) {
            int i = i0 + ty + 16 * v;
            g_m[(b * H_ + h) * T_ + i] = m_run[v];
            g_l[(b * H_ + h) * T_ + i] = l_run[v];
        }
    }
}

// ---------------- pass B (tensor cores): head-averaged attention ------------
// 128x128 lower-tri tiles (136/batch). 8 warps 2m x 4n, warp tile 64x32.
// Per head: load packed Qh/Ql/Kh/Kl tiles, 3-term bf16 MMA, exp-epilogue.
#define PB_ST 36
__global__ __launch_bounds__(256) void pass_b_mma(float* __restrict__ attn)
{
    extern __shared__ unsigned int smu[];
    unsigned int* Qh = smu;
    unsigned int* Ql = Qh + 128 * PB_ST;
    unsigned int* Kh = Ql + 128 * PB_ST;
    unsigned int* Kl = Kh + 128 * PB_ST;
    float* ms = (float*)(Kl + 128 * PB_ST);
    float* cs = ms + H_ * 128;

    // triangular tile index: p = i-block (0..15), jb = j-block (0..p)
    const int x = blockIdx.x;
    int p = (int)((sqrtf(8.f * x + 1.f) - 1.f) * 0.5f);
    while (p * (p + 1) / 2 > x) p--;
    while ((p + 1) * (p + 2) / 2 <= x) p++;
    const int jb = x - p * (p + 1) / 2;

    const int i0 = p * 128;
    const int j0 = jb * 128;
    const int b  = blockIdx.y;
    const int t  = threadIdx.x;
    const int wid  = t >> 5;
    const int lane = t & 31;
    const int g    = lane >> 2;
    const int tq   = lane & 3;
    const int wm   = (wid >> 2) * 64;
    const int wn   = (wid & 3) * 32;
    const bool diag = (p == jb);

    // preload softmax stats for this i-block, all heads
    for (int q = t; q < H_ * 128; q += 256) {
        int hh = q >> 7, rr = q & 127;
        ms[q] = g_m[(b * H_ + hh) * T_ + i0 + rr];
        cs[q] = 1.f / (16.f * g_l[(b * H_ + hh) * T_ + i0 + rr]);
    }

    float aacc[4][4][4];
#pragma unroll
    for (int mi = 0; mi < 4; mi++)
#pragma unroll
        for (int ni = 0; ni < 4; ni++)
#pragma unroll
            for (int e = 0; e < 4; e++) aacc[mi][ni][e] = 0.f;

    const int lrow = t >> 3;          // 0..31 -> x4 pages below
    const int lu4  = (t & 7) * 4;     // uint4 col offset

    for (int h = 0; h < H_; h++) {
        __syncthreads();
        // load 4 tiles: each 128 rows x 32 uints (8 uint4/row)
#pragma unroll
        for (int pp = 0; pp < 4; pp++) {
            const int row = lrow + 32 * pp;
            const long long qb = ((long long)(b * T_ + i0 + row)) * 512 + h * 32 + lu4;
            const long long kb = ((long long)(b * T_ + j0 + row)) * 512 + h * 32 + lu4;
            *(uint4*)&Qh[row * PB_ST + lu4] = *(const uint4*)&g_Qph[qb];
            *(uint4*)&Ql[row * PB_ST + lu4] = *(const uint4*)&g_Qpl[qb];
            *(uint4*)&Kh[row * PB_ST + lu4] = *(const uint4*)&g_Kph[kb];
            *(uint4*)&Kl[row * PB_ST + lu4] = *(const uint4*)&g_Kpl[kb];
        }
        __syncthreads();

#pragma unroll
        for (int mi = 0; mi < 4; mi++) {
            const int rowA = wm + mi * 16 + g;
            float s[4][4];
#pragma unroll
            for (int ni = 0; ni < 4; ni++)
#pragma unroll
                for (int e = 0; e < 4; e++) s[ni][e] = 0.f;

#pragma unroll
            for (int ks = 0; ks < 4; ks++) {
                const int kp0 = ks * 8 + tq;
                unsigned int ah[4], al[4];
                ah[0] = Qh[rowA * PB_ST + kp0];
                ah[1] = Qh[(rowA + 8) * PB_ST + kp0];
                ah[2] = Qh[rowA * PB_ST + kp0 + 4];
                ah[3] = Qh[(rowA + 8) * PB_ST + kp0 + 4];
                al[0] = Ql[rowA * PB_ST + kp0];
                al[1] = Ql[(rowA + 8) * PB_ST + kp0];
                al[2] = Ql[rowA * PB_ST + kp0 + 4];
                al[3] = Ql[(rowA + 8) * PB_ST + kp0 + 4];
#pragma unroll
                for (int ni = 0; ni < 4; ni++) {
                    const int col = wn + ni * 8 + g;
                    unsigned int bh[2], bl[2];
                    bh[0] = Kh[col * PB_ST + kp0];
                    bh[1] = Kh[col * PB_ST + kp0 + 4];
                    bl[0] = Kl[col * PB_ST + kp0];
                    bl[1] = Kl[col * PB_ST + kp0 + 4];
                    mma_bf16(s[ni], ah, bh);
                    mma_bf16(s[ni], ah, bl);
                    mma_bf16(s[ni], al, bh);
                }
            }

            // exp epilogue for this mi
            const int iA = i0 + rowA;
            const int iB = iA + 8;
            const float mA = ms[h * 128 + rowA];
            const float cA = cs[h * 128 + rowA];
            const float mB = ms[h * 128 + rowA + 8];
            const float cB = cs[h * 128 + rowA + 8];
            if (!diag) {
#pragma unroll
                for (int ni = 0; ni < 4; ni++) {
                    aacc[mi][ni][0] += __expf(s[ni][0] * 0.125f - mA) * cA;
                    aacc[mi][ni][1] += __expf(s[ni][1] * 0.125f - mA) * cA;
                    aacc[mi][ni][2] += __expf(s[ni][2] * 0.125f - mB) * cB;
                    aacc[mi][ni][3] += __expf(s[ni][3] * 0.125f - mB) * cB;
                }
            } else {
#pragma unroll
                for (int ni = 0; ni < 4; ni++) {
                    const int j = j0 + wn + ni * 8 + tq * 2;
                    if (j     <= iA) aacc[mi][ni][0] += __expf(s[ni][0] * 0.125f - mA) * cA;
                    if (j + 1 <= iA) aacc[mi][ni][1] += __expf(s[ni][1] * 0.125f - mA) * cA;
                    if (j     <= iB) aacc[mi][ni][2] += __expf(s[ni][2] * 0.125f - mB) * cB;
                    if (j + 1 <= iB) aacc[mi][ni][3] += __expf(s[ni][3] * 0.125f - mB) * cB;
                }
            }
        }
    }

    // write attn tile (masked elements hold 0)
#pragma unroll
    for (int mi = 0; mi < 4; mi++) {
        const int iA = i0 + wm + mi * 16 + g;
#pragma unroll
        for (int ni = 0; ni < 4; ni++) {
            const int j = j0 + wn + ni * 8 + tq * 2;
            *(float2*)&attn[((long long)(b * T_ + iA)) * T_ + j] =
                make_float2(aacc[mi][ni][0], aacc[mi][ni][1]);
            *(float2*)&attn[((long long)(b * T_ + iA + 8)) * T_ + j] =
                make_float2(aacc[mi][ni][2], aacc[mi][ni][3]);
        }
    }
}

// ---------------- launch ----------------------------------------------------
extern "C" void kernel_launch(void* const* d_in, const int* in_sizes, int n_in,
                              void* d_out, int out_size)
{
    const float* q  = (const float*)d_in[0];
    const float* k  = (const float*)d_in[1];
    const float* v  = (const float*)d_in[2];
    // d_in[3] = mask (tril) — causality applied analytically
    const float* Wq = (const float*)d_in[4];
    const float* Wk = (const float*)d_in[5];
    const float* Wv = (const float*)d_in[6];
    const float* Wo = (const float*)d_in[7];

    float* out  = (float*)d_out;
    float* attn = out + (long long)BT * DM;

    float *Qp, *Kp, *Vp, *O1p;
    cudaGetSymbolAddress((void**)&Qp,  g_Q);
    cudaGetSymbolAddress((void**)&Kp,  g_K);
    cudaGetSymbolAddress((void**)&Vp,  g_Vs);
    cudaGetSymbolAddress((void**)&O1p, g_o1);

    const int smem_a = 2 * 128 * PA_LD * 4;                        // 69632
    const int smem_bm = (4 * 128 * PB_ST + 2 * H_ * 128) * 4;      // 90112
    static bool attr_set = false;
    if (!attr_set) {
        cudaFuncSetAttribute(pass_a, cudaFuncAttributeMaxDynamicSharedMemorySize, smem_a);
        cudaFuncSetAttribute(pass_b_mma, cudaFuncAttributeMaxDynamicSharedMemorySize, smem_bm);
        attr_set = true;
    }

    // 0: zero attn (upper triangle is never touched by pass_b_mma)
    zero_kernel<<<2048, 256>>>(attn, (long long)BT * T_ / 4);

    // 1: fused Q and K projections on tensor cores (also emits packed bf16 Q/K)
    mmproj<<<dim3(DM / 128, BT / 128, 2), 256>>>(q, Wq, Qp, k, Wk, Kp);

    // 2: V projection
    sgemm128<<<dim3(1, BT / 128, 1), 256>>>(v, Wv, Vp, BT, DH, DM, 0, 0, 0);

    // 3: softmax stats
    pass_a<<<dim3(T_ / 128, H_, B_), 256, smem_a>>>();

    // 4: head-averaged attention matrix on tensor cores
    pass_b_mma<<<dim3(136, B_), 256, smem_bm>>>(attn);

    // 5: out1 = attn_avg @ V_shared
    sgemm128<<<dim3(1, T_ / 128, B_), 256>>>(attn, Vp, O1p, T_, DH, T_,
                                             (long long)T_ * T_,
                                             (long long)T_ * DH,
                                             (long long)T_ * DH);

    // 6: out = out1 @ Wo
    sgemm128<<<dim3(DM / 128, BT / 128, 1), 256>>>(O1p, Wo, out, BT, DM, DH, 0, 0, 0);
}

// round 17
// speedup vs baseline: 1.8333x; 1.1889x over previous
#include <cuda_runtime.h>
#include <cuda_bf16.h>
#include <cstdint>
#include <stdint.h>
#include <math.h>

#define B_  2
#define T_  2048
#define DM  1024
#define H_  16
#define DH  64
#define BT  (B_ * T_)   // 4096

// ---------------- scratch (static device globals; no runtime alloc) ----------
__device__ float g_Vs[(long long)BT * DH];    // 1 MB
__device__ float g_m[B_ * H_ * T_];
__device__ float g_l[B_ * H_ * T_];
__device__ float g_o1[(long long)BT * DH];    // 1 MB
// packed split-bf16 Q/K: bf16x2 pairs along d, [BT][512]
__device__ unsigned int g_Qph[(long long)BT * 512];
__device__ unsigned int g_Qpl[(long long)BT * 512];
__device__ unsigned int g_Kph[(long long)BT * 512];
__device__ unsigned int g_Kpl[(long long)BT * 512];

// ---------------- zero helper -----------------------------------------------
__global__ void zero_kernel(float* p, long long n4)
{
    long long i = blockIdx.x * (long long)blockDim.x + threadIdx.x;
    long long stride = (long long)gridDim.x * blockDim.x;
    float4 z = make_float4(0.f, 0.f, 0.f, 0.f);
    for (; i < n4; i += stride)
        ((float4*)p)[i] = z;
}

// ---------------- bf16 split helpers ----------------------------------------
__device__ __forceinline__ unsigned int bf16pair(float lo_elem, float hi_elem) {
    unsigned int r;
    asm("cvt.rn.bf16x2.f32 %0, %1, %2;" : "=r"(r) : "f"(hi_elem), "f"(lo_elem));
    return r;
}

__device__ __forceinline__ void split_pair(float x0, float x1,
                                           unsigned int& hp, unsigned int& lp) {
    hp = bf16pair(x0, x1);
    float h0 = __uint_as_float(hp << 16);
    float h1 = __uint_as_float(hp & 0xFFFF0000u);
    lp = bf16pair(x0 - h0, x1 - h1);
}

__device__ __forceinline__ void mma_bf16(float* c, const unsigned int* a,
                                         const unsigned int* b) {
    asm volatile(
        "mma.sync.aligned.m16n8k16.row.col.f32.bf16.bf16.f32 "
        "{%0,%1,%2,%3}, {%4,%5,%6,%7}, {%8,%9}, {%0,%1,%2,%3};"
        : "+f"(c[0]), "+f"(c[1]), "+f"(c[2]), "+f"(c[3])
        : "r"(a[0]), "r"(a[1]), "r"(a[2]), "r"(a[3]),
          "r"(b[0]), "r"(b[1]));
}

// ---------------- split-bf16 projection GEMM -> packed output only ----------
#define MM_LDP 136
__global__ __launch_bounds__(256, 2) void mmproj(
    const float* __restrict__ A,  const float* __restrict__ Bm,
    const float* __restrict__ A2, const float* __restrict__ B2)
{
    unsigned int* PH = g_Qph;
    unsigned int* PL = g_Qpl;
    if (blockIdx.z == 1) { A = A2; Bm = B2; PH = g_Kph; PL = g_Kpl; }
    const int K = DM, N = DM;

    __shared__ unsigned int Aph[8][MM_LDP], Apl[8][MM_LDP];
    __shared__ unsigned int Bph[8][MM_LDP], Bpl[8][MM_LDP];

    const int t    = threadIdx.x;
    const int wid  = t >> 5;
    const int lane = t & 31;
    const int g    = lane >> 2;
    const int tq   = lane & 3;
    const int wm   = (wid >> 2) * 64;
    const int wn   = (wid & 3) * 32;
    const int m0   = blockIdx.y * 128;
    const int n0   = blockIdx.x * 128;

    float acc[4][4][4];
#pragma unroll
    for (int mi = 0; mi < 4; mi++)
#pragma unroll
        for (int ni = 0; ni < 4; ni++)
#pragma unroll
            for (int e = 0; e < 4; e++) acc[mi][ni][e] = 0.f;

    const int am   = t & 127;
    const int ak   = (t >> 7) * 8;
    const int ak2  = ak >> 1;
    const int rp   = t >> 5;
    const int bc   = (t & 31) * 4;

    for (int k0 = 0; k0 < K; k0 += 16) {
        float4 av0 = *(const float4*)&A [(long long)(m0 + am) * K + k0 + ak];
        float4 av1 = *(const float4*)&A [(long long)(m0 + am) * K + k0 + ak + 4];
        float4 bv0 = *(const float4*)&Bm[(long long)(k0 + 2 * rp)     * N + n0 + bc];
        float4 bv1 = *(const float4*)&Bm[(long long)(k0 + 2 * rp + 1) * N + n0 + bc];

        __syncthreads();

        {
            float va[8] = {av0.x, av0.y, av0.z, av0.w, av1.x, av1.y, av1.z, av1.w};
#pragma unroll
            for (int i = 0; i < 4; i++) {
                unsigned int hp, lp;
                split_pair(va[2 * i], va[2 * i + 1], hp, lp);
                Aph[ak2 + i][am] = hp;
                Apl[ak2 + i][am] = lp;
            }
        }
        {
            float r0[4] = {bv0.x, bv0.y, bv0.z, bv0.w};
            float r1[4] = {bv1.x, bv1.y, bv1.z, bv1.w};
#pragma unroll
            for (int c = 0; c < 4; c++) {
                unsigned int hp, lp;
                split_pair(r0[c], r1[c], hp, lp);
                Bph[rp][bc + c] = hp;
                Bpl[rp][bc + c] = lp;
            }
        }
        __syncthreads();

        unsigned int bh[4][2], bl[4][2];
#pragma unroll
        for (int ni = 0; ni < 4; ni++) {
            const int col = wn + ni * 8 + g;
            bh[ni][0] = Bph[tq][col];
            bh[ni][1] = Bph[tq + 4][col];
            bl[ni][0] = Bpl[tq][col];
            bl[ni][1] = Bpl[tq + 4][col];
        }
#pragma unroll
        for (int mi = 0; mi < 4; mi++) {
            const int row = wm + mi * 16 + g;
            unsigned int ah[4], al[4];
            ah[0] = Aph[tq][row];
            ah[1] = Aph[tq][row + 8];
            ah[2] = Aph[tq + 4][row];
            ah[3] = Aph[tq + 4][row + 8];
            al[0] = Apl[tq][row];
            al[1] = Apl[tq][row + 8];
            al[2] = Apl[tq + 4][row];
            al[3] = Apl[tq + 4][row + 8];
#pragma unroll
            for (int ni = 0; ni < 4; ni++) {
                mma_bf16(acc[mi][ni], ah, bh[ni]);
                mma_bf16(acc[mi][ni], ah, bl[ni]);
                mma_bf16(acc[mi][ni], al, bh[ni]);
            }
        }
    }

    // epilogue: packed split-bf16 only (pairs are consecutive cols)
#pragma unroll
    for (int mi = 0; mi < 4; mi++) {
        const int row = m0 + wm + mi * 16 + g;
#pragma unroll
        for (int ni = 0; ni < 4; ni++) {
            const int col = n0 + wn + ni * 8 + tq * 2;
            const int pc = col >> 1;
            unsigned int hp, lp;
            split_pair(acc[mi][ni][0], acc[mi][ni][1], hp, lp);
            PH[(long long)row * 512 + pc] = hp;
            PL[(long long)row * 512 + pc] = lp;
            split_pair(acc[mi][ni][2], acc[mi][ni][3], hp, lp);
            PH[(long long)(row + 8) * 512 + pc] = hp;
            PL[(long long)(row + 8) * 512 + pc] = lp;
        }
    }
}

// ---------------- generic tiled SGEMM: C = A[MxK] * B[KxN] ------------------
__global__ __launch_bounds__(256) void sgemm128(
    const float* __restrict__ A, const float* __restrict__ Bm,
    float* __restrict__ C, int M, int N, int K,
    long long sA, long long sB, long long sC)
{
    A  += (long long)blockIdx.z * sA;
    Bm += (long long)blockIdx.z * sB;
    C  += (long long)blockIdx.z * sC;

    __shared__ float As[8][132];
    __shared__ float Bs[8][132];

    const int t  = threadIdx.x;
    const int tx = t % 16;
    const int ty = t / 16;
    const int m0 = blockIdx.y * 128;
    const int n0 = blockIdx.x * 128;

    float acc[8][8];
#pragma unroll
    for (int i = 0; i < 8; i++)
#pragma unroll
        for (int j = 0; j < 8; j++) acc[i][j] = 0.f;

    for (int k0 = 0; k0 < K; k0 += 8) {
#pragma unroll
        for (int p = 0; p < 4; p++) {
            int idx = t + 256 * p;
            int m = idx >> 3, k = idx & 7;
            int gm = m0 + m;
            As[k][m] = (gm < M) ? A[(long long)gm * K + (k0 + k)] : 0.f;
        }
#pragma unroll
        for (int p = 0; p < 4; p++) {
            int idx = t + 256 * p;
            int k = idx >> 7, n = idx & 127;
            int gn = n0 + n;
            Bs[k][n] = (gn < N) ? Bm[(long long)(k0 + k) * N + gn] : 0.f;
        }
        __syncthreads();

#pragma unroll
        for (int kk = 0; kk < 8; kk++) {
            float a[8], b[8];
#pragma unroll
            for (int i = 0; i < 4; i++) {
                a[i]     = As[kk][ty * 4 + i];
                a[4 + i] = As[kk][64 + ty * 4 + i];
            }
#pragma unroll
            for (int j = 0; j < 4; j++) {
                b[j]     = Bs[kk][tx * 4 + j];
                b[4 + j] = Bs[kk][64 + tx * 4 + j];
            }
#pragma unroll
            for (int i = 0; i < 8; i++)
#pragma unroll
                for (int j = 0; j < 8; j++)
                    acc[i][j] += a[i] * b[j];
        }
        __syncthreads();
    }

#pragma unroll
    for (int i = 0; i < 8; i++) {
        int gm = m0 + ((i < 4) ? (ty * 4 + i) : (64 + ty * 4 + (i - 4)));
        if (gm >= M) continue;
#pragma unroll
        for (int j = 0; j < 8; j++) {
            int gn = n0 + ((j < 4) ? (tx * 4 + j) : (64 + tx * 4 + (j - 4)));
            if (gn < N) C[(long long)gm * N + gn] = acc[i][j];
        }
    }
}

// ---------------- pass A (tensor cores): online softmax stats ---------------
// grid (16, H, B); p = 15-bx (LPT). Block: 128 q rows of one head, loop over
// causal K tiles; online (m,l) per thread-row, merged once per head.
#define PB_ST 36
__global__ __launch_bounds__(256) void pass_a_mma()
{
    extern __shared__ unsigned int smu[];
    unsigned int* Qh = smu;                       // 128*36
    unsigned int* Ql = Qh + 128 * PB_ST;
    unsigned int* Kh = Ql + 128 * PB_ST;
    unsigned int* Kl = Kh + 128 * PB_ST;
    float2* mlred = (float2*)(Kl + 128 * PB_ST);  // [4][128]

    const int p  = 15 - (int)blockIdx.x;          // LPT: big blocks first
    const int i0 = p * 128;
    const int h  = blockIdx.y;
    const int b  = blockIdx.z;
    const int t  = threadIdx.x;
    const int wid  = t >> 5;
    const int lane = t & 31;
    const int g    = lane >> 2;
    const int tq   = lane & 3;
    const int wm   = (wid >> 2) * 64;
    const int wnb  = wid & 3;
    const int wn   = wnb * 32;

    const int lrow = t >> 3;
    const int lu4  = (t & 7) * 4;

    // load Q tiles for this (i-block, head)
#pragma unroll
    for (int pp = 0; pp < 4; pp++) {
        const int row = lrow + 32 * pp;
        const long long qb = ((long long)(b * T_ + i0 + row)) * 512 + h * 32 + lu4;
        *(uint4*)&Qh[row * PB_ST + lu4] = *(const uint4*)&g_Qph[qb];
        *(uint4*)&Ql[row * PB_ST + lu4] = *(const uint4*)&g_Qpl[qb];
    }

    float mr[4][2], lr[4][2];
#pragma unroll
    for (int mi = 0; mi < 4; mi++) {
        mr[mi][0] = -INFINITY; mr[mi][1] = -INFINITY;
        lr[mi][0] = 0.f;       lr[mi][1] = 0.f;
    }

    for (int jt = 0; jt <= p; jt++) {
        const int j0 = jt * 128;
        __syncthreads();
#pragma unroll
        for (int pp = 0; pp < 4; pp++) {
            const int row = lrow + 32 * pp;
            const long long kb = ((long long)(b * T_ + j0 + row)) * 512 + h * 32 + lu4;
            *(uint4*)&Kh[row * PB_ST + lu4] = *(const uint4*)&g_Kph[kb];
            *(uint4*)&Kl[row * PB_ST + lu4] = *(const uint4*)&g_Kpl[kb];
        }
        __syncthreads();
        const bool diag = (jt == p);

#pragma unroll
        for (int mi = 0; mi < 4; mi++) {
            const int rowA = wm + mi * 16 + g;
            float s[4][4];
#pragma unroll
            for (int ni = 0; ni < 4; ni++)
#pragma unroll
                for (int e = 0; e < 4; e++) s[ni][e] = 0.f;

#pragma unroll
            for (int ks = 0; ks < 4; ks++) {
                const int kp0 = ks * 8 + tq;
                unsigned int ah[4], al[4];
                ah[0] = Qh[rowA * PB_ST + kp0];
                ah[1] = Qh[(rowA + 8) * PB_ST + kp0];
                ah[2] = Qh[rowA * PB_ST + kp0 + 4];
                ah[3] = Qh[(rowA + 8) * PB_ST + kp0 + 4];
                al[0] = Ql[rowA * PB_ST + kp0];
                al[1] = Ql[(rowA + 8) * PB_ST + kp0];
                al[2] = Ql[rowA * PB_ST + kp0 + 4];
                al[3] = Ql[(rowA + 8) * PB_ST + kp0 + 4];
#pragma unroll
                for (int ni = 0; ni < 4; ni++) {
                    const int col = wn + ni * 8 + g;
                    unsigned int bh[2], bl[2];
                    bh[0] = Kh[col * PB_ST + kp0];
                    bh[1] = Kh[col * PB_ST + kp0 + 4];
                    bl[0] = Kl[col * PB_ST + kp0];
                    bl[1] = Kl[col * PB_ST + kp0 + 4];
                    mma_bf16(s[ni], ah, bh);
                    mma_bf16(s[ni], ah, bl);
                    mma_bf16(s[ni], al, bh);
                }
            }

            // scale + causal mask + online update for the two row slices
            const int iA = i0 + rowA;
            const int iB = iA + 8;
            float t0 = -INFINITY, t1 = -INFINITY;
#pragma unroll
            for (int ni = 0; ni < 4; ni++) {
                const int j = j0 + wn + ni * 8 + tq * 2;
                s[ni][0] = (!diag || j     <= iA) ? s[ni][0] * 0.125f : -INFINITY;
                s[ni][1] = (!diag || j + 1 <= iA) ? s[ni][1] * 0.125f : -INFINITY;
                s[ni][2] = (!diag || j     <= iB) ? s[ni][2] * 0.125f : -INFINITY;
                s[ni][3] = (!diag || j + 1 <= iB) ? s[ni][3] * 0.125f : -INFINITY;
                t0 = fmaxf(t0, fmaxf(s[ni][0], s[ni][1]));
                t1 = fmaxf(t1, fmaxf(s[ni][2], s[ni][3]));
            }
            {
                float nm = fmaxf(mr[mi][0], t0);
                if (nm > -INFINITY) {
                    float ps = 0.f;
#pragma unroll
                    for (int ni = 0; ni < 4; ni++)
                        ps += __expf(s[ni][0] - nm) + __expf(s[ni][1] - nm);
                    lr[mi][0] = lr[mi][0] * __expf(mr[mi][0] - nm) + ps;
                    mr[mi][0] = nm;
                }
            }
            {
                float nm = fmaxf(mr[mi][1], t1);
                if (nm > -INFINITY) {
                    float ps = 0.f;
#pragma unroll
                    for (int ni = 0; ni < 4; ni++)
                        ps += __expf(s[ni][2] - nm) + __expf(s[ni][3] - nm);
                    lr[mi][1] = lr[mi][1] * __expf(mr[mi][1] - nm) + ps;
                    mr[mi][1] = nm;
                }
            }
        }
    }

    // merge across tq group (lanes g*4 + tq; xor 1,2 stay in group)
#pragma unroll
    for (int mi = 0; mi < 4; mi++)
#pragma unroll
        for (int sub = 0; sub < 2; sub++) {
            float m = mr[mi][sub], l = lr[mi][sub];
#pragma unroll
            for (int o = 1; o < 4; o <<= 1) {
                float mo = __shfl_xor_sync(0xffffffffu, m, o);
                float lo = __shfl_xor_sync(0xffffffffu, l, o);
                float nm = fmaxf(m, mo);
                if (nm == -INFINITY) { l = 0.f; }
                else l = l * __expf(m - nm) + lo * __expf(mo - nm);
                m = nm;
            }
            mr[mi][sub] = m; lr[mi][sub] = l;
        }

    __syncthreads();
    if (tq == 0) {
#pragma unroll
        for (int mi = 0; mi < 4; mi++)
#pragma unroll
            for (int sub = 0; sub < 2; sub++) {
                const int row = wm + mi * 16 + sub * 8 + g;
                mlred[wnb * 128 + row] = make_float2(mr[mi][sub], lr[mi][sub]);
            }
    }
    __syncthreads();
    if (t < 128) {
        float2 a = mlred[t];
#pragma unroll
        for (int w = 1; w < 4; w++) {
            float2 c = mlred[w * 128 + t];
            float nm = fmaxf(a.x, c.x);
            if (nm == -INFINITY) { a = make_float2(nm, 0.f); }
            else a = make_float2(nm, a.y * __expf(a.x - nm) + c.y * __expf(c.x - nm));
        }
        g_m[(b * H_ + h) * T_ + i0 + t] = a.x;
        g_l[(b * H_ + h) * T_ + i0 + t] = a.y;
    }
}

// ---------------- pass B (tensor cores): head-averaged attention ------------
__global__ __launch_bounds__(256) void pass_b_mma(float* __restrict__ attn)
{
    extern __shared__ unsigned int smu[];
    unsigned int* Qh = smu;
    unsigned int* Ql = Qh + 128 * PB_ST;
    unsigned int* Kh = Ql + 128 * PB_ST;
    unsigned int* Kl = Kh + 128 * PB_ST;
    float* ms = (float*)(Kl + 128 * PB_ST);
    float* cs = ms + H_ * 128;

    // triangular tile index: p = i-block (0..15), jb = j-block (0..p)
    const int x = blockIdx.x;
    int p = (int)((sqrtf(8.f * x + 1.f) - 1.f) * 0.5f);
    while (p * (p + 1) / 2 > x) p--;
    while ((p + 1) * (p + 2) / 2 <= x) p++;
    const int jb = x - p * (p + 1) / 2;

    const int i0 = p * 128;
    const int j0 = jb * 128;
    const int b  = blockIdx.y;
    const int t  = threadIdx.x;
    const int wid  = t >> 5;
    const int lane = t & 31;
    const int g    = lane >> 2;
    const int tq   = lane & 3;
    const int wm   = (wid >> 2) * 64;
    const int wn   = (wid & 3) * 32;
    const bool diag = (p == jb);

    for (int q = t; q < H_ * 128; q += 256) {
        int hh = q >> 7, rr = q & 127;
        ms[q] = g_m[(b * H_ + hh) * T_ + i0 + rr];
        cs[q] = 1.f / (16.f * g_l[(b * H_ + hh) * T_ + i0 + rr]);
    }

    float aacc[4][4][4];
#pragma unroll
    for (int mi = 0; mi < 4; mi++)
#pragma unroll
        for (int ni = 0; ni < 4; ni++)
#pragma unroll
            for (int e = 0; e < 4; e++) aacc[mi][ni][e] = 0.f;

    const int lrow = t >> 3;
    const int lu4  = (t & 7) * 4;

    for (int h = 0; h < H_; h++) {
        __syncthreads();
#pragma unroll
        for (int pp = 0; pp < 4; pp++) {
            const int row = lrow + 32 * pp;
            const long long qb = ((long long)(b * T_ + i0 + row)) * 512 + h * 32 + lu4;
            const long long kb = ((long long)(b * T_ + j0 + row)) * 512 + h * 32 + lu4;
            *(uint4*)&Qh[row * PB_ST + lu4] = *(const uint4*)&g_Qph[qb];
            *(uint4*)&Ql[row * PB_ST + lu4] = *(const uint4*)&g_Qpl[qb];
            *(uint4*)&Kh[row * PB_ST + lu4] = *(const uint4*)&g_Kph[kb];
            *(uint4*)&Kl[row * PB_ST + lu4] = *(const uint4*)&g_Kpl[kb];
        }
        __syncthreads();

#pragma unroll
        for (int mi = 0; mi < 4; mi++) {
            const int rowA = wm + mi * 16 + g;
            float s[4][4];
#pragma unroll
            for (int ni = 0; ni < 4; ni++)
#pragma unroll
                for (int e = 0; e < 4; e++) s[ni][e] = 0.f;

#pragma unroll
            for (int ks = 0; ks < 4; ks++) {
                const int kp0 = ks * 8 + tq;
                unsigned int ah[4], al[4];
                ah[0] = Qh[rowA * PB_ST + kp0];
                ah[1] = Qh[(rowA + 8) * PB_ST + kp0];
                ah[2] = Qh[rowA * PB_ST + kp0 + 4];
                ah[3] = Qh[(rowA + 8) * PB_ST + kp0 + 4];
                al[0] = Ql[rowA * PB_ST + kp0];
                al[1] = Ql[(rowA + 8) * PB_ST + kp0];
                al[2] = Ql[rowA * PB_ST + kp0 + 4];
                al[3] = Ql[(rowA + 8) * PB_ST + kp0 + 4];
#pragma unroll
                for (int ni = 0; ni < 4; ni++) {
                    const int col = wn + ni * 8 + g;
                    unsigned int bh[2], bl[2];
                    bh[0] = Kh[col * PB_ST + kp0];
                    bh[1] = Kh[col * PB_ST + kp0 + 4];
                    bl[0] = Kl[col * PB_ST + kp0];
                    bl[1] = Kl[col * PB_ST + kp0 + 4];
                    mma_bf16(s[ni], ah, bh);
                    mma_bf16(s[ni], ah, bl);
                    mma_bf16(s[ni], al, bh);
                }
            }

            const int iA = i0 + rowA;
            const int iB = iA + 8;
            const float mA = ms[h * 128 + rowA];
            const float cA = cs[h * 128 + rowA];
            const float mB = ms[h * 128 + rowA + 8];
            const float cB = cs[h * 128 + rowA + 8];
            if (!diag) {
#pragma unroll
                for (int ni = 0; ni < 4; ni++) {
                    aacc[mi][ni][0] += __expf(s[ni][0] * 0.125f - mA) * cA;
                    aacc[mi][ni][1] += __expf(s[ni][1] * 0.125f - mA) * cA;
                    aacc[mi][ni][2] += __expf(s[ni][2] * 0.125f - mB) * cB;
                    aacc[mi][ni][3] += __expf(s[ni][3] * 0.125f - mB) * cB;
                }
            } else {
#pragma unroll
                for (int ni = 0; ni < 4; ni++) {
                    const int j = j0 + wn + ni * 8 + tq * 2;
                    if (j     <= iA) aacc[mi][ni][0] += __expf(s[ni][0] * 0.125f - mA) * cA;
                    if (j + 1 <= iA) aacc[mi][ni][1] += __expf(s[ni][1] * 0.125f - mA) * cA;
                    if (j     <= iB) aacc[mi][ni][2] += __expf(s[ni][2] * 0.125f - mB) * cB;
                    if (j + 1 <= iB) aacc[mi][ni][3] += __expf(s[ni][3] * 0.125f - mB) * cB;
                }
            }
        }
    }

#pragma unroll
    for (int mi = 0; mi < 4; mi++) {
        const int iA = i0 + wm + mi * 16 + g;
#pragma unroll
        for (int ni = 0; ni < 4; ni++) {
            const int j = j0 + wn + ni * 8 + tq * 2;
            *(float2*)&attn[((long long)(b * T_ + iA)) * T_ + j] =
                make_float2(aacc[mi][ni][0], aacc[mi][ni][1]);
            *(float2*)&attn[((long long)(b * T_ + iA + 8)) * T_ + j] =
                make_float2(aacc[mi][ni][2], aacc[mi][ni][3]);
        }
    }
}

// ---------------- launch ----------------------------------------------------
extern "C" void kernel_launch(void* const* d_in, const int* in_sizes, int n_in,
                              void* d_out, int out_size)
{
    const float* q  = (const float*)d_in[0];
    const float* k  = (const float*)d_in[1];
    const float* v  = (const float*)d_in[2];
    // d_in[3] = mask (tril) — causality applied analytically
    const float* Wq = (const float*)d_in[4];
    const float* Wk = (const float*)d_in[5];
    const float* Wv = (const float*)d_in[6];
    const float* Wo = (const float*)d_in[7];

    float* out  = (float*)d_out;
    float* attn = out + (long long)BT * DM;

    float *Vp, *O1p;
    cudaGetSymbolAddress((void**)&Vp,  g_Vs);
    cudaGetSymbolAddress((void**)&O1p, g_o1);

    const int smem_am = (4 * 128 * PB_ST) * 4 + 4 * 128 * 8;       // 77824
    const int smem_bm = (4 * 128 * PB_ST + 2 * H_ * 128) * 4;      // 90112
    static bool attr_set = false;
    if (!attr_set) {
        cudaFuncSetAttribute(pass_a_mma, cudaFuncAttributeMaxDynamicSharedMemorySize, smem_am);
        cudaFuncSetAttribute(pass_b_mma, cudaFuncAttributeMaxDynamicSharedMemorySize, smem_bm);
        attr_set = true;
    }

    // 0: zero attn (upper triangle is never touched by pass_b_mma)
    zero_kernel<<<2048, 256>>>(attn, (long long)BT * T_ / 4);

    // 1: fused Q and K projections on tensor cores -> packed split-bf16 only
    mmproj<<<dim3(DM / 128, BT / 128, 2), 256>>>(q, Wq, k, Wk);

    // 2: V projection
    sgemm128<<<dim3(1, BT / 128, 1), 256>>>(v, Wv, Vp, BT, DH, DM, 0, 0, 0);

    // 3: softmax stats on tensor cores
    pass_a_mma<<<dim3(16, H_, B_), 256, smem_am>>>();

    // 4: head-averaged attention matrix on tensor cores
    pass_b_mma<<<dim3(136, B_), 256, smem_bm>>>(attn);

    // 5: out1 = attn_avg @ V_shared
    sgemm128<<<dim3(1, T_ / 128, B_), 256>>>(attn, Vp, O1p, T_, DH, T_,
                                             (long long)T_ * T_,
                                             (long long)T_ * DH,
                                             (long long)T_ * DH);

    // 6: out = out1 @ Wo
    sgemm128<<<dim3(DM / 128, BT / 128, 1), 256>>>(O1p, Wo, out, BT, DM, DH, 0, 0, 0);
}